// round 7
// baseline (speedup 1.0000x reference)
#include <cuda_runtime.h>
#include <cstdint>

// Problem constants
#define BB  2
#define TT  2048
#define DD  1024
#define HH  16
#define D3  3072   // 3*D

// Scratch (allocation-free rule: __device__ globals)
__device__ float g_qkv[(size_t)BB * TT * D3];    // qkv projection (tf32-rounded)
__device__ float g_vals[(size_t)BB * TT * DD];   // attn@V (tf32-rounded)
__device__ float g_x[(size_t)BB * TT * DD];      // x, tf32-rounded
__device__ float g_wqkv[(size_t)DD * D3];        // W_qkv, tf32-rounded
__device__ float g_wout[(size_t)DD * DD];        // W_out, tf32-rounded

// ---------------------------------------------------------------------------
// tf32 helpers
// ---------------------------------------------------------------------------
__device__ __forceinline__ unsigned f2tf(float x) {
    unsigned r;
    asm("cvt.rna.tf32.f32 %0, %1;" : "=r"(r) : "f"(x));
    return r;
}

__device__ __forceinline__ void mma_tf32(float c[4],
                                         unsigned a0, unsigned a1, unsigned a2, unsigned a3,
                                         unsigned b0, unsigned b1) {
    asm volatile(
        "mma.sync.aligned.m16n8k8.row.col.f32.tf32.tf32.f32 "
        "{%0,%1,%2,%3}, {%4,%5,%6,%7}, {%8,%9}, {%0,%1,%2,%3};"
        : "+f"(c[0]), "+f"(c[1]), "+f"(c[2]), "+f"(c[3])
        : "r"(a0), "r"(a1), "r"(a2), "r"(a3), "r"(b0), "r"(b1));
}

__device__ __forceinline__ void cp16(unsigned* smem_dst, const void* gsrc) {
    unsigned s = (unsigned)__cvta_generic_to_shared(smem_dst);
    asm volatile("cp.async.cg.shared.global [%0], [%1], 16;" :: "r"(s), "l"(gsrc));
}
#define CP_COMMIT() asm volatile("cp.async.commit_group;")
#define CP_WAIT1()  asm volatile("cp.async.wait_group 1;")

// ---------------------------------------------------------------------------
// Elementwise tf32 rounding (prep pass; RNA once per value)
// ---------------------------------------------------------------------------
__global__ void round_tf32_kernel(const float4* __restrict__ in,
                                  float4* __restrict__ out, int n4)
{
    int i = blockIdx.x * blockDim.x + threadIdx.x;
    if (i < n4) {
        float4 v = in[i];
        out[i] = make_float4(__uint_as_float(f2tf(v.x)), __uint_as_float(f2tf(v.y)),
                             __uint_as_float(f2tf(v.z)), __uint_as_float(f2tf(v.w)));
    }
}

// ---------------------------------------------------------------------------
// NN GEMM + bias, tf32, 3-stage cp.async, one sync/iter. Inputs are already
// tf32-rounded fp32 bits -> NO CVTs in the hot loop.
// ---------------------------------------------------------------------------
#define GA 2560              // A stage words: 128*20
#define GB 2176              // B stage words: 16*136
#define GEMM_SMEM ((3 * (GA + GB)) * 4)   // 56832 B

template <bool ROUND_OUT>
__global__ void __launch_bounds__(256, 2) gemm_tf32_bias(
    const float* __restrict__ A, const float* __restrict__ Bm,
    const float* __restrict__ bias, float* __restrict__ C,
    int M, int N, int K)
{
    extern __shared__ unsigned gsm[];
    unsigned* As = gsm;
    unsigned* Bs = gsm + 3 * GA;

    const int tid = threadIdx.x;
    const int w   = tid >> 5;
    const int ln  = tid & 31;
    const int gid = ln >> 2;
    const int tig = ln & 3;
    const int wm  = (w & 3) * 32;
    const int wn  = (w >> 2) * 64;
    const int m0  = blockIdx.y * 128;
    const int n0  = blockIdx.x * 128;

    const int arow = tid >> 2;
    const int ac4  = (tid & 3) << 2;
    const int brow = tid >> 5;
    const int bc4  = (tid & 31) << 2;

    const int nk = K >> 4;

    auto issue = [&](int kt, int s) {
        int k0 = kt << 4;
        unsigned* as = As + s * GA;
        unsigned* bs = Bs + s * GB;
        cp16(&as[arow * 20 + ac4],        &A[(size_t)(m0 + arow) * K + k0 + ac4]);
        cp16(&as[(arow + 64) * 20 + ac4], &A[(size_t)(m0 + arow + 64) * K + k0 + ac4]);
        cp16(&bs[brow * 136 + bc4],       &Bm[(size_t)(k0 + brow) * N + n0 + bc4]);
        cp16(&bs[(brow + 8) * 136 + bc4], &Bm[(size_t)(k0 + brow + 8) * N + n0 + bc4]);
    };

    float acc[2][8][4];
#pragma unroll
    for (int i = 0; i < 2; i++)
#pragma unroll
        for (int j = 0; j < 8; j++)
#pragma unroll
            for (int t = 0; t < 4; t++) acc[i][j][t] = 0.f;

    issue(0, 0); CP_COMMIT();
    issue(1, 1); CP_COMMIT();

    for (int kt = 0; kt < nk; kt++) {
        CP_WAIT1();
        __syncthreads();
        if (kt + 2 < nk) issue(kt + 2, (kt + 2) % 3);
        CP_COMMIT();

        const unsigned* as = As + (kt % 3) * GA;
        const unsigned* bs = Bs + (kt % 3) * GB;
#pragma unroll
        for (int ks = 0; ks < 2; ks++) {
            unsigned af[2][4], bf[8][2];
#pragma unroll
            for (int mt = 0; mt < 2; mt++) {
                int base = (wm + mt * 16 + gid) * 20 + ks * 8 + tig;
                af[mt][0] = as[base];
                af[mt][1] = as[base + 8 * 20];
                af[mt][2] = as[base + 4];
                af[mt][3] = as[base + 8 * 20 + 4];
            }
#pragma unroll
            for (int nt = 0; nt < 8; nt++) {
                int base = (ks * 8 + tig) * 136 + wn + nt * 8 + gid;
                bf[nt][0] = bs[base];
                bf[nt][1] = bs[base + 4 * 136];
            }
#pragma unroll
            for (int mt = 0; mt < 2; mt++)
#pragma unroll
                for (int nt = 0; nt < 8; nt++)
                    mma_tf32(acc[mt][nt], af[mt][0], af[mt][1], af[mt][2], af[mt][3],
                             bf[nt][0], bf[nt][1]);
        }
    }

#pragma unroll
    for (int mt = 0; mt < 2; mt++) {
#pragma unroll
        for (int nt = 0; nt < 8; nt++) {
            int n = n0 + wn + nt * 8 + 2 * tig;
            float2 bb = *reinterpret_cast<const float2*>(&bias[n]);
            int m = m0 + wm + mt * 16 + gid;
            float v00 = acc[mt][nt][0] + bb.x, v01 = acc[mt][nt][1] + bb.y;
            float v10 = acc[mt][nt][2] + bb.x, v11 = acc[mt][nt][3] + bb.y;
            if (ROUND_OUT) {
                v00 = __uint_as_float(f2tf(v00));
                v01 = __uint_as_float(f2tf(v01));
                v10 = __uint_as_float(f2tf(v10));
                v11 = __uint_as_float(f2tf(v11));
            }
            *reinterpret_cast<float2*>(&C[(size_t)m * N + n])       = make_float2(v00, v01);
            *reinterpret_cast<float2*>(&C[(size_t)(m + 8) * N + n]) = make_float2(v10, v11);
        }
    }
}

// ---------------------------------------------------------------------------
// Fused attention: 128-thread CTAs over 64 q-rows, 32-key chunks, 3-stage
// cp.async, target 4 CTAs/SM (16 warps/SM). Streaming attn stores (__stcs).
// g_qkv values are tf32-exact; epilogue rounds g_vals for CVT-free out-proj.
// ---------------------------------------------------------------------------
#define KSS 68
#define VSS 72
#define KCH 32
#define KSTG (KCH * KSS)                  // 2176 words
#define VSTG (KCH * VSS)                  // 2304 words
#define ATTN_SMEM ((3 * (KSTG + VSTG)) * 4)   // 53760 B

__global__ void __launch_bounds__(128, 4) fused_attn(float* __restrict__ attn)
{
    extern __shared__ unsigned sm[];
    unsigned* KsB = sm;                  // 3 stages of [32][68]
    unsigned* VsB = sm + 3 * KSTG;       // 3 stages of [32][72]

    const int z  = blockIdx.y;
    const int b  = z >> 4;
    const int h  = z & 15;
    const int m0 = blockIdx.x * 64;

    const float* Qb = g_qkv + (size_t)b * TT * D3 + h * 192;
    const float* Kb = Qb + 64;
    const float* Vb = Qb + 128;
    float* S = attn + (size_t)z * TT * TT;

    const int tid = threadIdx.x;
    const int w   = tid >> 5;            // 0..3
    const int ln  = tid & 31;
    const int gid = ln >> 2;
    const int tig = ln & 3;
    const int wm  = w * 16;
    const int r2  = tid >> 2;            // 0..31
    const int c16 = (tid & 3) << 4;      // 0,16,32,48

    auto issueK = [&](int ck, int s) {
        const float* src = Kb + (size_t)(ck * KCH + r2) * D3 + c16;
        unsigned* dst = KsB + s * KSTG + r2 * KSS + c16;
#pragma unroll
        for (int j = 0; j < 4; j++) cp16(dst + j * 4, src + j * 4);
    };
    auto issueKV = [&](int ck, int s) {
        const float* srcK = Kb + (size_t)(ck * KCH + r2) * D3 + c16;
        const float* srcV = Vb + (size_t)(ck * KCH + r2) * D3 + c16;
        unsigned* dK = KsB + s * KSTG + r2 * KSS + c16;
        unsigned* dV = VsB + s * VSTG + r2 * VSS + c16;
#pragma unroll
        for (int j = 0; j < 4; j++) { cp16(dK + j * 4, srcK + j * 4); cp16(dV + j * 4, srcV + j * 4); }
    };

    // ---- stage Q (64 rows) into K stages 0/1, extract per-warp A fragments
    {
        const int r = tid >> 1, half = tid & 1;
        const unsigned* src = reinterpret_cast<const unsigned*>(Qb + (size_t)(m0 + r) * D3) + half * 32;
        unsigned* dst = KsB + (r >> 5) * KSTG + (r & 31) * KSS + half * 32;
#pragma unroll
        for (int j = 0; j < 8; j++)
            *reinterpret_cast<uint4*>(dst + j * 4) = *reinterpret_cast<const uint4*>(src + j * 4);
    }
    __syncthreads();
    unsigned qf[8][4];
    {
        const unsigned* qbuf = KsB + (wm >> 5) * KSTG;
        const int qr = (wm & 31) + gid;
#pragma unroll
        for (int kc = 0; kc < 8; kc++) {
            qf[kc][0] = qbuf[qr * KSS + kc * 8 + tig];
            qf[kc][1] = qbuf[(qr + 8) * KSS + kc * 8 + tig];
            qf[kc][2] = qbuf[qr * KSS + kc * 8 + tig + 4];
            qf[kc][3] = qbuf[(qr + 8) * KSS + kc * 8 + tig + 4];
        }
    }
    __syncthreads();

    // ---- pass 1: rowsums of exp(s/8), 64 chunks of 32 keys
    issueK(0, 0); CP_COMMIT();
    issueK(1, 1); CP_COMMIT();

    float rsum0 = 0.f, rsum1 = 0.f;
    for (int ck = 0; ck < 64; ck++) {
        CP_WAIT1();
        __syncthreads();
        if (ck + 2 < 64) issueK(ck + 2, (ck + 2) % 3);
        CP_COMMIT();

        const unsigned* ks = KsB + (ck % 3) * KSTG;
#pragma unroll
        for (int nt = 0; nt < 4; nt++) {
            float sacc[4] = {0.f, 0.f, 0.f, 0.f};
#pragma unroll
            for (int kc = 0; kc < 8; kc++) {
                unsigned b0 = ks[(nt * 8 + gid) * KSS + kc * 8 + tig];
                unsigned b1 = ks[(nt * 8 + gid) * KSS + kc * 8 + tig + 4];
                mma_tf32(sacc, qf[kc][0], qf[kc][1], qf[kc][2], qf[kc][3], b0, b1);
            }
            rsum0 += __expf(sacc[0] * 0.125f) + __expf(sacc[1] * 0.125f);
            rsum1 += __expf(sacc[2] * 0.125f) + __expf(sacc[3] * 0.125f);
        }
    }
    rsum0 += __shfl_xor_sync(0xffffffffu, rsum0, 1);
    rsum0 += __shfl_xor_sync(0xffffffffu, rsum0, 2);
    rsum1 += __shfl_xor_sync(0xffffffffu, rsum1, 1);
    rsum1 += __shfl_xor_sync(0xffffffffu, rsum1, 2);
    const float inv0 = 1.0f / rsum0;
    const float inv1 = 1.0f / rsum1;

    __syncthreads();   // pass-1 readers done before pass-2 prologue overwrites

    // ---- pass 2: recompute S, write normalized attn (streaming), O = P@V
    float oacc[8][4];
#pragma unroll
    for (int dt = 0; dt < 8; dt++)
#pragma unroll
        for (int t = 0; t < 4; t++) oacc[dt][t] = 0.f;

    issueKV(0, 0); CP_COMMIT();
    issueKV(1, 1); CP_COMMIT();

    float* Sr0 = S + (size_t)(m0 + wm + gid) * TT + 2 * tig;
    float* Sr1 = S + (size_t)(m0 + wm + gid + 8) * TT + 2 * tig;
    const int srcLo = (ln & ~3) | (tig >> 1);
    const int srcHi = srcLo + 2;

    for (int ck = 0; ck < 64; ck++) {
        CP_WAIT1();
        __syncthreads();
        if (ck + 2 < 64) issueKV(ck + 2, (ck + 2) % 3);
        CP_COMMIT();

        const unsigned* ks = KsB + (ck % 3) * KSTG;
        const unsigned* vs = VsB + (ck % 3) * VSTG;

#pragma unroll
        for (int nt = 0; nt < 4; nt++) {
            float sacc[4] = {0.f, 0.f, 0.f, 0.f};
#pragma unroll
            for (int kc = 0; kc < 8; kc++) {
                unsigned b0 = ks[(nt * 8 + gid) * KSS + kc * 8 + tig];
                unsigned b1 = ks[(nt * 8 + gid) * KSS + kc * 8 + tig + 4];
                mma_tf32(sacc, qf[kc][0], qf[kc][1], qf[kc][2], qf[kc][3], b0, b1);
            }
            float p0 = __expf(sacc[0] * 0.125f) * inv0;
            float p1 = __expf(sacc[1] * 0.125f) * inv0;
            float p2 = __expf(sacc[2] * 0.125f) * inv1;
            float p3 = __expf(sacc[3] * 0.125f) * inv1;

            __stcs(reinterpret_cast<float2*>(Sr0 + ck * KCH + nt * 8), make_float2(p0, p1));
            __stcs(reinterpret_cast<float2*>(Sr1 + ck * KCH + nt * 8), make_float2(p2, p3));

            // P accumulator -> A fragment via intra-quad shuffles, RNA-rounded
            float x0 = __shfl_sync(0xffffffffu, p0, srcLo);
            float x1 = __shfl_sync(0xffffffffu, p1, srcLo);
            float y0 = __shfl_sync(0xffffffffu, p0, srcHi);
            float y1 = __shfl_sync(0xffffffffu, p1, srcHi);
            float z0 = __shfl_sync(0xffffffffu, p2, srcLo);
            float z1 = __shfl_sync(0xffffffffu, p3, srcLo);
            float w0 = __shfl_sync(0xffffffffu, p2, srcHi);
            float w1 = __shfl_sync(0xffffffffu, p3, srcHi);
            unsigned a0 = f2tf((tig & 1) ? x1 : x0);
            unsigned a1 = f2tf((tig & 1) ? z1 : z0);
            unsigned a2 = f2tf((tig & 1) ? y1 : y0);
            unsigned a3 = f2tf((tig & 1) ? w1 : w0);

#pragma unroll
            for (int dt = 0; dt < 8; dt++) {
                unsigned b0 = vs[(nt * 8 + tig) * VSS + dt * 8 + gid];
                unsigned b1 = vs[(nt * 8 + tig + 4) * VSS + dt * 8 + gid];
                mma_tf32(oacc[dt], a0, a1, a2, a3, b0, b1);
            }
        }
    }

    // ---- epilogue: tf32-rounded O -> g_vals (so out-proj is CVT-free)
    float* Ob = g_vals + (size_t)b * TT * DD + h * 64;
#pragma unroll
    for (int dt = 0; dt < 8; dt++) {
        *reinterpret_cast<float2*>(Ob + (size_t)(m0 + wm + gid) * DD + dt * 8 + 2 * tig) =
            make_float2(__uint_as_float(f2tf(oacc[dt][0])), __uint_as_float(f2tf(oacc[dt][1])));
        *reinterpret_cast<float2*>(Ob + (size_t)(m0 + wm + gid + 8) * DD + dt * 8 + 2 * tig) =
            make_float2(__uint_as_float(f2tf(oacc[dt][2])), __uint_as_float(f2tf(oacc[dt][3])));
    }
}

// ---------------------------------------------------------------------------
extern "C" void kernel_launch(void* const* d_in, const int* in_sizes, int n_in,
                              void* d_out, int out_size)
{
    const float* x      = (const float*)d_in[0];
    const float* W_qkv  = (const float*)d_in[1];
    const float* b_qkv  = (const float*)d_in[2];
    const float* W_out  = (const float*)d_in[3];
    const float* b_out  = (const float*)d_in[4];

    float* out  = (float*)d_out;
    float* attn = out + (size_t)BB * TT * DD;

    static float *qkv_s = nullptr, *vals_s = nullptr, *x_s = nullptr,
                 *wqkv_s = nullptr, *wout_s = nullptr;
    static bool inited = false;
    if (!inited) {
        cudaGetSymbolAddress((void**)&qkv_s, g_qkv);
        cudaGetSymbolAddress((void**)&vals_s, g_vals);
        cudaGetSymbolAddress((void**)&x_s, g_x);
        cudaGetSymbolAddress((void**)&wqkv_s, g_wqkv);
        cudaGetSymbolAddress((void**)&wout_s, g_wout);
        cudaFuncSetAttribute(fused_attn, cudaFuncAttributeMaxDynamicSharedMemorySize, ATTN_SMEM);
        cudaFuncSetAttribute(fused_attn, cudaFuncAttributePreferredSharedMemoryCarveout, 100);
        cudaFuncSetAttribute(gemm_tf32_bias<true>,  cudaFuncAttributeMaxDynamicSharedMemorySize, GEMM_SMEM);
        cudaFuncSetAttribute(gemm_tf32_bias<true>,  cudaFuncAttributePreferredSharedMemoryCarveout, 100);
        cudaFuncSetAttribute(gemm_tf32_bias<false>, cudaFuncAttributeMaxDynamicSharedMemorySize, GEMM_SMEM);
        cudaFuncSetAttribute(gemm_tf32_bias<false>, cudaFuncAttributePreferredSharedMemoryCarveout, 100);
        inited = true;
    }

    // 0) Pre-round inputs to the tf32 grid (RNA, once per value)
    {
        int n4x = (BB * TT * DD) / 4;
        round_tf32_kernel<<<(n4x + 255) / 256, 256>>>((const float4*)x, (float4*)x_s, n4x);
        int n4w = (DD * D3) / 4;
        round_tf32_kernel<<<(n4w + 255) / 256, 256>>>((const float4*)W_qkv, (float4*)wqkv_s, n4w);
        int n4o = (DD * DD) / 4;
        round_tf32_kernel<<<(n4o + 255) / 256, 256>>>((const float4*)W_out, (float4*)wout_s, n4o);
    }

    // 1) QKV projection (tf32-exact inputs; output rounded for fused kernel)
    gemm_tf32_bias<true><<<dim3(D3 / 128, (BB * TT) / 128), 256, GEMM_SMEM>>>(
        x_s, wqkv_s, b_qkv, qkv_s, BB * TT, D3, DD);

    // 2) Fused scores + softmax + AV: writes attn (d_out) and g_vals
    fused_attn<<<dim3(TT / 64, BB * HH), 128, ATTN_SMEM>>>(attn);

    // 3) Output projection (tf32-exact inputs; exact fp32 output)
    gemm_tf32_bias<false><<<dim3(DD / 128, (BB * TT) / 128), 256, GEMM_SMEM>>>(
        vals_s, wout_s, b_out, out, BB * TT, DD, DD);
}

// round 9
// speedup vs baseline: 2.0361x; 2.0361x over previous
#include <cuda_runtime.h>
#include <cuda_fp16.h>
#include <cstdint>

// Problem constants
#define BB  2
#define TT  2048
#define DD  1024
#define HH  16
#define D3  3072   // 3*D

// Scratch (allocation-free rule: __device__ globals), all 16B-aligned
__device__ __align__(16) __half g_xh  [(size_t)BB * TT * DD];   // x, fp16
__device__ __align__(16) __half g_wqkvh[(size_t)D3 * DD];       // W_qkv^T [3072][1024] fp16
__device__ __align__(16) __half g_wouth[(size_t)DD * DD];       // W_out^T [1024][1024] fp16
__device__ __align__(16) __half g_qkvh[(size_t)BB * TT * D3];   // qkv, fp16
__device__ __align__(16) __half g_valsh[(size_t)BB * TT * DD];  // attn@V, fp16

// ---------------------------------------------------------------------------
// helpers
// ---------------------------------------------------------------------------
__device__ __forceinline__ void mma_f16(float c[4],
                                        unsigned a0, unsigned a1, unsigned a2, unsigned a3,
                                        unsigned b0, unsigned b1) {
    asm volatile(
        "mma.sync.aligned.m16n8k16.row.col.f32.f16.f16.f32 "
        "{%0,%1,%2,%3}, {%4,%5,%6,%7}, {%8,%9}, {%0,%1,%2,%3};"
        : "+f"(c[0]), "+f"(c[1]), "+f"(c[2]), "+f"(c[3])
        : "r"(a0), "r"(a1), "r"(a2), "r"(a3), "r"(b0), "r"(b1));
}

__device__ __forceinline__ void cp16(unsigned* smem_dst, const void* gsrc) {
    unsigned s = (unsigned)__cvta_generic_to_shared(smem_dst);
    asm volatile("cp.async.cg.shared.global [%0], [%1], 16;" :: "r"(s), "l"(gsrc));
}
#define CP_COMMIT() asm volatile("cp.async.commit_group;")
#define CP_WAIT1()  asm volatile("cp.async.wait_group 1;")

__device__ __forceinline__ uint32_t smem_u32(const void* p) {
    uint32_t a;
    asm("{ .reg .u64 t; cvta.to.shared.u64 t, %1; cvt.u32.u64 %0, t; }" : "=r"(a) : "l"(p));
    return a;
}

__device__ __forceinline__ unsigned pack_h2(float lo, float hi) {
    __half2 h = __floats2half2_rn(lo, hi);
    return *reinterpret_cast<unsigned*>(&h);
}

// ---------------------------------------------------------------------------
// Prep kernels
// ---------------------------------------------------------------------------
__global__ void round_f16_kernel(const float4* __restrict__ in,
                                 __half2* __restrict__ out, int n4)
{
    int i = blockIdx.x * blockDim.x + threadIdx.x;
    if (i < n4) {
        float4 v = in[i];
        out[2 * i]     = __floats2half2_rn(v.x, v.y);
        out[2 * i + 1] = __floats2half2_rn(v.z, v.w);
    }
}

// out[n][k] = half(in[k][n]); grid (N/32, K/32), block (32,8)
__global__ void transpose_f16_kernel(const float* __restrict__ in,
                                     __half* __restrict__ out, int K, int N)
{
    __shared__ float t[32][33];
    const int bx = blockIdx.x * 32;   // n
    const int by = blockIdx.y * 32;   // k
    const int x = threadIdx.x, y = threadIdx.y;
#pragma unroll
    for (int i = 0; i < 32; i += 8)
        t[y + i][x] = in[(size_t)(by + y + i) * N + bx + x];
    __syncthreads();
#pragma unroll
    for (int i = 0; i < 32; i += 8)
        out[(size_t)(bx + y + i) * K + by + x] = __float2half_rn(t[x][y + i]);
}

// ---------------------------------------------------------------------------
// fp16 NT GEMM + bias: C[M,N] = A[M,K] @ Bt[N,K]^T + bias[N].
// BM=128, BN=128, BK=32 halves. 256 threads, 3-stage cp.async, 1 sync/iter.
// Warp tile 32x64: 2(m16) x 8(n8) x 2(k16) mma per BK.
// ---------------------------------------------------------------------------
#define GSTR 20                          // u32 stride per row (16 data + 4 pad)
#define GST  (128 * GSTR)                // stage words (A or B): 2560
#define GEMM_SMEM (3 * 2 * GST * 4)      // 61440 B

template <bool OUT_HALF>
__global__ void __launch_bounds__(256, 2) gemm_f16(
    const __half* __restrict__ A, const __half* __restrict__ Bt,
    const float* __restrict__ bias, void* __restrict__ Cv,
    int M, int N, int K)
{
    extern __shared__ unsigned gsm[];
    unsigned* As = gsm;
    unsigned* Bs = gsm + 3 * GST;

    const int tid = threadIdx.x;
    const int w   = tid >> 5;
    const int ln  = tid & 31;
    const int gid = ln >> 2;
    const int tig = ln & 3;
    const int wm  = (w & 3) * 32;
    const int wn  = (w >> 2) * 64;
    const int m0  = blockIdx.y * 128;
    const int n0  = blockIdx.x * 128;

    const int nk = K >> 5;               // BK = 32 halves

    auto fill = [&](int kt, int s) {
        int k0 = kt << 5;
        unsigned* as = As + s * GST;
        unsigned* bs = Bs + s * GST;
#pragma unroll
        for (int it = 0; it < 2; it++) {
            int lin = it * 256 + tid;
            int row = lin >> 2, j = lin & 3;        // 4 x 16B per row
            cp16(&as[row * GSTR + j * 4], A  + (size_t)(m0 + row) * K + k0 + j * 8);
            cp16(&bs[row * GSTR + j * 4], Bt + (size_t)(n0 + row) * K + k0 + j * 8);
        }
        CP_COMMIT();
    };

    float acc[2][8][4];
#pragma unroll
    for (int i = 0; i < 2; i++)
#pragma unroll
        for (int j = 0; j < 8; j++)
#pragma unroll
            for (int t = 0; t < 4; t++) acc[i][j][t] = 0.f;

    fill(0, 0);
    fill(1, 1);

    for (int kt = 0; kt < nk; kt++) {
        CP_WAIT1();
        __syncthreads();
        if (kt + 2 < nk) fill(kt + 2, (kt + 2) % 3);
        else CP_COMMIT();

        const unsigned* as = As + (kt % 3) * GST;
        const unsigned* bs = Bs + (kt % 3) * GST;
#pragma unroll
        for (int kc = 0; kc < 2; kc++) {
            unsigned af[2][4], bf[8][2];
#pragma unroll
            for (int mt = 0; mt < 2; mt++) {
                int base = (wm + mt * 16 + gid) * GSTR + kc * 8 + tig;
                af[mt][0] = as[base];
                af[mt][1] = as[base + 8 * GSTR];
                af[mt][2] = as[base + 4];
                af[mt][3] = as[base + 8 * GSTR + 4];
            }
#pragma unroll
            for (int nt = 0; nt < 8; nt++) {
                int base = (wn + nt * 8 + gid) * GSTR + kc * 8 + tig;
                bf[nt][0] = bs[base];
                bf[nt][1] = bs[base + 4];
            }
#pragma unroll
            for (int mt = 0; mt < 2; mt++)
#pragma unroll
                for (int nt = 0; nt < 8; nt++)
                    mma_f16(acc[mt][nt], af[mt][0], af[mt][1], af[mt][2], af[mt][3],
                            bf[nt][0], bf[nt][1]);
        }
    }

#pragma unroll
    for (int mt = 0; mt < 2; mt++) {
#pragma unroll
        for (int nt = 0; nt < 8; nt++) {
            int n = n0 + wn + nt * 8 + 2 * tig;
            float2 bb = *reinterpret_cast<const float2*>(&bias[n]);
            int m = m0 + wm + mt * 16 + gid;
            float v00 = acc[mt][nt][0] + bb.x, v01 = acc[mt][nt][1] + bb.y;
            float v10 = acc[mt][nt][2] + bb.x, v11 = acc[mt][nt][3] + bb.y;
            if (OUT_HALF) {
                __half* C = (__half*)Cv;
                *reinterpret_cast<__half2*>(&C[(size_t)m * N + n])       = __floats2half2_rn(v00, v01);
                *reinterpret_cast<__half2*>(&C[(size_t)(m + 8) * N + n]) = __floats2half2_rn(v10, v11);
            } else {
                float* C = (float*)Cv;
                *reinterpret_cast<float2*>(&C[(size_t)m * N + n])       = make_float2(v00, v01);
                *reinterpret_cast<float2*>(&C[(size_t)(m + 8) * N + n]) = make_float2(v10, v11);
            }
        }
    }
}

// ---------------------------------------------------------------------------
// Fused attention (fp16): q-tile 128, 64-key chunks, 3-stage cp.async,
// one sync/iter. Scores: NT fp16 mma (4 per 8-key frag). AV: P-fragments
// come straight from score C-frags (no shuffles); V B-frags via
// ldmatrix.x4.trans.  attn written fp32 (normalized); O -> g_valsh fp16.
// ---------------------------------------------------------------------------
#define KSTR 36                            // u32 per row (32 data + 4 pad)
#define KCH  64                            // keys per chunk
#define KSTG (KCH * KSTR)                  // 2304 words
#define ATTN_SMEM (3 * 2 * KSTG * 4)       // 55296 B

__global__ void __launch_bounds__(256, 2) fused_attn(float* __restrict__ attn)
{
    extern __shared__ unsigned sm[];
    unsigned* KsB = sm;                    // 3 stages [64][36]
    unsigned* VsB = sm + 3 * KSTG;         // 3 stages [64][36]
    const uint32_t vs_base = smem_u32(VsB);

    const int z  = blockIdx.y;
    const int b  = z >> 4;
    const int h  = z & 15;
    const int m0 = blockIdx.x * 128;

    const __half* Qb = g_qkvh + (size_t)b * TT * D3 + h * 192;
    const __half* Kb = Qb + 64;
    const __half* Vb = Qb + 128;
    float* S = attn + (size_t)z * TT * TT;

    const int tid = threadIdx.x;
    const int w   = tid >> 5;
    const int ln  = tid & 31;
    const int gid = ln >> 2;
    const int tig = ln & 3;
    const int wm  = w * 16;

    auto issueK = [&](int ck, int s) {
#pragma unroll
        for (int it = 0; it < 2; it++) {
            int lin = it * 256 + tid;
            int row = lin >> 3, j = lin & 7;       // 8 x 16B per row (64 halves)
            cp16(&KsB[s * KSTG + row * KSTR + j * 4],
                 Kb + (size_t)(ck * KCH + row) * D3 + j * 8);
        }
        CP_COMMIT();
    };
    auto issueKV = [&](int ck, int s) {
#pragma unroll
        for (int it = 0; it < 2; it++) {
            int lin = it * 256 + tid;
            int row = lin >> 3, j = lin & 7;
            cp16(&KsB[s * KSTG + row * KSTR + j * 4],
                 Kb + (size_t)(ck * KCH + row) * D3 + j * 8);
            cp16(&VsB[s * KSTG + row * KSTR + j * 4],
                 Vb + (size_t)(ck * KCH + row) * D3 + j * 8);
        }
        CP_COMMIT();
    };

    // ---- stage Q (fp16) into K stages 0/1, extract per-warp A fragments
    {
#pragma unroll
        for (int it = 0; it < 4; it++) {
            int lin = it * 256 + tid;
            int row = lin >> 3, j = lin & 7;
            unsigned* dst = KsB + (row >> 6) * KSTG + (row & 63) * KSTR + j * 4;
            *reinterpret_cast<uint4*>(dst) =
                *(reinterpret_cast<const uint4*>(Qb + (size_t)(m0 + row) * D3) + j);
        }
    }
    __syncthreads();
    unsigned qf[4][4];
    {
        const unsigned* qbuf = KsB + (wm >> 6) * KSTG;
        const int qr = (wm & 63) + gid;
#pragma unroll
        for (int kc = 0; kc < 4; kc++) {
            qf[kc][0] = qbuf[qr * KSTR + kc * 8 + tig];
            qf[kc][1] = qbuf[(qr + 8) * KSTR + kc * 8 + tig];
            qf[kc][2] = qbuf[qr * KSTR + kc * 8 + tig + 4];
            qf[kc][3] = qbuf[(qr + 8) * KSTR + kc * 8 + tig + 4];
        }
    }
    __syncthreads();

    // ---- pass 1: rowsums of exp(s/8)
    issueK(0, 0);
    issueK(1, 1);

    float rsum0 = 0.f, rsum1 = 0.f;
    for (int ck = 0; ck < 32; ck++) {
        CP_WAIT1();
        __syncthreads();
        if (ck + 2 < 32) issueK(ck + 2, (ck + 2) % 3);
        else CP_COMMIT();

        const unsigned* ks = KsB + (ck % 3) * KSTG;
#pragma unroll
        for (int nt = 0; nt < 8; nt++) {
            float sacc[4] = {0.f, 0.f, 0.f, 0.f};
#pragma unroll
            for (int kc = 0; kc < 4; kc++) {
                int base = (nt * 8 + gid) * KSTR + kc * 8 + tig;
                mma_f16(sacc, qf[kc][0], qf[kc][1], qf[kc][2], qf[kc][3],
                        ks[base], ks[base + 4]);
            }
            rsum0 += __expf(sacc[0] * 0.125f) + __expf(sacc[1] * 0.125f);
            rsum1 += __expf(sacc[2] * 0.125f) + __expf(sacc[3] * 0.125f);
        }
    }
    rsum0 += __shfl_xor_sync(0xffffffffu, rsum0, 1);
    rsum0 += __shfl_xor_sync(0xffffffffu, rsum0, 2);
    rsum1 += __shfl_xor_sync(0xffffffffu, rsum1, 1);
    rsum1 += __shfl_xor_sync(0xffffffffu, rsum1, 2);
    const float inv0 = 1.0f / rsum0;
    const float inv1 = 1.0f / rsum1;

    __syncthreads();

    // ---- pass 2
    float oacc[8][4];
#pragma unroll
    for (int dt = 0; dt < 8; dt++)
#pragma unroll
        for (int t = 0; t < 4; t++) oacc[dt][t] = 0.f;

    issueKV(0, 0);
    issueKV(1, 1);

    float* Sr0 = S + (size_t)(m0 + wm + gid) * TT + 2 * tig;
    float* Sr1 = S + (size_t)(m0 + wm + gid + 8) * TT + 2 * tig;

    // ldmatrix.x4.trans per-thread address pieces (within a V stage)
    const int li  = ln >> 3;             // matrix index 0..3
    const int lsub = ln & 7;
    const uint32_t ldm_off = (uint32_t)(((li & 1) * 8 + lsub) * (KSTR * 4) + ((li >> 1) * 8) * 2);

    for (int ck = 0; ck < 32; ck++) {
        CP_WAIT1();
        __syncthreads();
        if (ck + 2 < 32) issueKV(ck + 2, (ck + 2) % 3);
        else CP_COMMIT();

        const unsigned* ks = KsB + (ck % 3) * KSTG;
        const uint32_t vstage = vs_base + (uint32_t)((ck % 3) * KSTG * 4);

#pragma unroll
        for (int j = 0; j < 4; j++) {    // 16 keys per j (two 8-key frags)
            float s0[4] = {0.f, 0.f, 0.f, 0.f};
            float s1[4] = {0.f, 0.f, 0.f, 0.f};
#pragma unroll
            for (int kc = 0; kc < 4; kc++) {
                int b0 = ((2 * j) * 8 + gid) * KSTR + kc * 8 + tig;
                int b1 = ((2 * j + 1) * 8 + gid) * KSTR + kc * 8 + tig;
                mma_f16(s0, qf[kc][0], qf[kc][1], qf[kc][2], qf[kc][3], ks[b0], ks[b0 + 4]);
                mma_f16(s1, qf[kc][0], qf[kc][1], qf[kc][2], qf[kc][3], ks[b1], ks[b1 + 4]);
            }
            float p00 = __expf(s0[0] * 0.125f) * inv0;
            float p01 = __expf(s0[1] * 0.125f) * inv0;
            float p02 = __expf(s0[2] * 0.125f) * inv1;
            float p03 = __expf(s0[3] * 0.125f) * inv1;
            float p10 = __expf(s1[0] * 0.125f) * inv0;
            float p11 = __expf(s1[1] * 0.125f) * inv0;
            float p12 = __expf(s1[2] * 0.125f) * inv1;
            float p13 = __expf(s1[3] * 0.125f) * inv1;

            *reinterpret_cast<float2*>(Sr0 + ck * KCH + (2 * j) * 8)     = make_float2(p00, p01);
            *reinterpret_cast<float2*>(Sr1 + ck * KCH + (2 * j) * 8)     = make_float2(p02, p03);
            *reinterpret_cast<float2*>(Sr0 + ck * KCH + (2 * j + 1) * 8) = make_float2(p10, p11);
            *reinterpret_cast<float2*>(Sr1 + ck * KCH + (2 * j + 1) * 8) = make_float2(p12, p13);

            // A fragment = packed C fragment (fp16 layout identity)
            unsigned a0 = pack_h2(p00, p01);
            unsigned a1 = pack_h2(p02, p03);
            unsigned a2 = pack_h2(p10, p11);
            unsigned a3 = pack_h2(p12, p13);

            const uint32_t kbase = vstage + (uint32_t)(j * 16 * (KSTR * 4)) + ldm_off;
#pragma unroll
            for (int dtp = 0; dtp < 4; dtp++) {   // 16 d-columns per ldmatrix
                unsigned r0, r1, r2, r3;
                asm volatile(
                    "ldmatrix.sync.aligned.m8n8.x4.trans.shared.b16 {%0,%1,%2,%3}, [%4];"
                    : "=r"(r0), "=r"(r1), "=r"(r2), "=r"(r3)
                    : "r"(kbase + (uint32_t)(dtp * 32)));
                mma_f16(oacc[2 * dtp],     a0, a1, a2, a3, r0, r1);
                mma_f16(oacc[2 * dtp + 1], a0, a1, a2, a3, r2, r3);
            }
        }
    }

    // ---- epilogue: O -> g_valsh (fp16, feeds out-proj directly)
    __half* Ob = g_valsh + (size_t)b * TT * DD + h * 64;
#pragma unroll
    for (int dt = 0; dt < 8; dt++) {
        *reinterpret_cast<__half2*>(Ob + (size_t)(m0 + wm + gid) * DD + dt * 8 + 2 * tig) =
            __floats2half2_rn(oacc[dt][0], oacc[dt][1]);
        *reinterpret_cast<__half2*>(Ob + (size_t)(m0 + wm + gid + 8) * DD + dt * 8 + 2 * tig) =
            __floats2half2_rn(oacc[dt][2], oacc[dt][3]);
    }
}

// ---------------------------------------------------------------------------
extern "C" void kernel_launch(void* const* d_in, const int* in_sizes, int n_in,
                              void* d_out, int out_size)
{
    const float* x      = (const float*)d_in[0];
    const float* W_qkv  = (const float*)d_in[1];
    const float* b_qkv  = (const float*)d_in[2];
    const float* W_out  = (const float*)d_in[3];
    const float* b_out  = (const float*)d_in[4];

    float* out  = (float*)d_out;
    float* attn = out + (size_t)BB * TT * DD;

    static __half *xh = nullptr, *wqkvh = nullptr, *wouth = nullptr,
                  *qkvh = nullptr, *valsh = nullptr;
    static bool inited = false;
    if (!inited) {
        cudaGetSymbolAddress((void**)&xh, g_xh);
        cudaGetSymbolAddress((void**)&wqkvh, g_wqkvh);
        cudaGetSymbolAddress((void**)&wouth, g_wouth);
        cudaGetSymbolAddress((void**)&qkvh, g_qkvh);
        cudaGetSymbolAddress((void**)&valsh, g_valsh);
        cudaFuncSetAttribute(fused_attn, cudaFuncAttributeMaxDynamicSharedMemorySize, ATTN_SMEM);
        cudaFuncSetAttribute(fused_attn, cudaFuncAttributePreferredSharedMemoryCarveout, 100);
        cudaFuncSetAttribute(gemm_f16<true>,  cudaFuncAttributeMaxDynamicSharedMemorySize, GEMM_SMEM);
        cudaFuncSetAttribute(gemm_f16<true>,  cudaFuncAttributePreferredSharedMemoryCarveout, 100);
        cudaFuncSetAttribute(gemm_f16<false>, cudaFuncAttributeMaxDynamicSharedMemorySize, GEMM_SMEM);
        cudaFuncSetAttribute(gemm_f16<false>, cudaFuncAttributePreferredSharedMemoryCarveout, 100);
        inited = true;
    }

    // 0) Prep: x -> fp16; weights -> transposed fp16
    {
        int n4x = (BB * TT * DD) / 4;
        round_f16_kernel<<<(n4x + 255) / 256, 256>>>((const float4*)x, (__half2*)xh, n4x);
        transpose_f16_kernel<<<dim3(D3 / 32, DD / 32), dim3(32, 8)>>>(W_qkv, wqkvh, DD, D3);
        transpose_f16_kernel<<<dim3(DD / 32, DD / 32), dim3(32, 8)>>>(W_out, wouth, DD, DD);
    }

    // 1) QKV projection (fp16 in, fp16 out)
    gemm_f16<true><<<dim3(D3 / 128, (BB * TT) / 128), 256, GEMM_SMEM>>>(
        xh, wqkvh, b_qkv, qkvh, BB * TT, D3, DD);

    // 2) Fused scores + softmax + AV: writes attn (d_out fp32) and g_valsh
    fused_attn<<<dim3(TT / 128, BB * HH), 256, ATTN_SMEM>>>(attn);

    // 3) Output projection (fp16 in, fp32 out)
    gemm_f16<false><<<dim3(DD / 128, (BB * TT) / 128), 256, GEMM_SMEM>>>(
        valsh, wouth, b_out, out, BB * TT, DD, DD);
}

// round 10
// speedup vs baseline: 2.0994x; 1.0311x over previous
#include <cuda_runtime.h>
#include <cuda_fp16.h>
#include <cstdint>

// Problem constants
#define BB  2
#define TT  2048
#define DD  1024
#define HH  16
#define D3  3072   // 3*D

// Scratch (allocation-free rule: __device__ globals), all 16B-aligned
__device__ __align__(16) __half g_xh  [(size_t)BB * TT * DD];
__device__ __align__(16) __half g_wqkvh[(size_t)D3 * DD];       // W_qkv^T [3072][1024]
__device__ __align__(16) __half g_wouth[(size_t)DD * DD];       // W_out^T [1024][1024]
__device__ __align__(16) __half g_qkvh[(size_t)BB * TT * D3];
__device__ __align__(16) __half g_valsh[(size_t)BB * TT * DD];

// ---------------------------------------------------------------------------
// helpers
// ---------------------------------------------------------------------------
__device__ __forceinline__ void mma_f16(float c[4],
                                        unsigned a0, unsigned a1, unsigned a2, unsigned a3,
                                        unsigned b0, unsigned b1) {
    asm volatile(
        "mma.sync.aligned.m16n8k16.row.col.f32.f16.f16.f32 "
        "{%0,%1,%2,%3}, {%4,%5,%6,%7}, {%8,%9}, {%0,%1,%2,%3};"
        : "+f"(c[0]), "+f"(c[1]), "+f"(c[2]), "+f"(c[3])
        : "r"(a0), "r"(a1), "r"(a2), "r"(a3), "r"(b0), "r"(b1));
}

__device__ __forceinline__ void ldm_x4(unsigned& r0, unsigned& r1, unsigned& r2, unsigned& r3,
                                       uint32_t addr) {
    asm volatile("ldmatrix.sync.aligned.m8n8.x4.shared.b16 {%0,%1,%2,%3}, [%4];"
                 : "=r"(r0), "=r"(r1), "=r"(r2), "=r"(r3) : "r"(addr));
}

__device__ __forceinline__ void cp16(unsigned* smem_dst, const void* gsrc) {
    unsigned s = (unsigned)__cvta_generic_to_shared(smem_dst);
    asm volatile("cp.async.cg.shared.global [%0], [%1], 16;" :: "r"(s), "l"(gsrc));
}
#define CP_COMMIT() asm volatile("cp.async.commit_group;")
#define CP_WAIT1()  asm volatile("cp.async.wait_group 1;")

__device__ __forceinline__ uint32_t smem_u32(const void* p) {
    uint32_t a;
    asm("{ .reg .u64 t; cvta.to.shared.u64 t, %1; cvt.u32.u64 %0, t; }" : "=r"(a) : "l"(p));
    return a;
}

__device__ __forceinline__ unsigned pack_h2(float lo, float hi) {
    __half2 h = __floats2half2_rn(lo, hi);
    return *reinterpret_cast<unsigned*>(&h);
}

// ---------------------------------------------------------------------------
// Prep kernels
// ---------------------------------------------------------------------------
__global__ void round_f16_kernel(const float4* __restrict__ in,
                                 __half2* __restrict__ out, int n4)
{
    int i = blockIdx.x * blockDim.x + threadIdx.x;
    if (i < n4) {
        float4 v = in[i];
        out[2 * i]     = __floats2half2_rn(v.x, v.y);
        out[2 * i + 1] = __floats2half2_rn(v.z, v.w);
    }
}

__global__ void transpose_f16_kernel(const float* __restrict__ in,
                                     __half* __restrict__ out, int K, int N)
{
    __shared__ float t[32][33];
    const int bx = blockIdx.x * 32;   // n
    const int by = blockIdx.y * 32;   // k
    const int x = threadIdx.x, y = threadIdx.y;
#pragma unroll
    for (int i = 0; i < 32; i += 8)
        t[y + i][x] = in[(size_t)(by + y + i) * N + bx + x];
    __syncthreads();
#pragma unroll
    for (int i = 0; i < 32; i += 8)
        out[(size_t)(bx + y + i) * K + by + x] = __float2half_rn(t[x][y + i]);
}

// ---------------------------------------------------------------------------
// fp16 NT GEMM + bias: C[M,N] = A[M,K] @ Bt[N,K]^T + bias[N].
// BM=128, BN=128, BK=32 halves. 256 threads, 3-stage cp.async, 1 sync/iter.
// Fragments via ldmatrix.x4 (12 per k-step vs 48 scalar LDS).
// ---------------------------------------------------------------------------
#define GSTR 20                          // u32 stride per row (16 data + 4 pad)
#define GST  (128 * GSTR)
#define GEMM_SMEM (3 * 2 * GST * 4)      // 61440 B

template <bool OUT_HALF>
__global__ void __launch_bounds__(256, 2) gemm_f16(
    const __half* __restrict__ A, const __half* __restrict__ Bt,
    const float* __restrict__ bias, void* __restrict__ Cv,
    int M, int N, int K)
{
    extern __shared__ unsigned gsm[];
    unsigned* As = gsm;
    unsigned* Bs = gsm + 3 * GST;
    const uint32_t as_base = smem_u32(As);
    const uint32_t bs_base = smem_u32(Bs);

    const int tid = threadIdx.x;
    const int w   = tid >> 5;
    const int ln  = tid & 31;
    const int gid = ln >> 2;
    const int tig = ln & 3;
    const int wm  = (w & 3) * 32;
    const int wn  = (w >> 2) * 64;
    const int m0  = blockIdx.y * 128;
    const int n0  = blockIdx.x * 128;

    // ldmatrix per-thread address components
    const int a_row = (ln & 7) + ((ln >> 3) & 1) * 8;     // 0..15
    const int a_k   = (ln >> 4) * 4;                      // 0 or 4 (u32)
    const int b_row = (ln & 7) + (ln >> 4) * 8;           // 0..15 (nt pair local)
    const int b_k   = ((ln >> 3) & 1) * 4;                // 0 or 4 (u32)

    const int nk = K >> 5;

    auto fill = [&](int kt, int s) {
        int k0 = kt << 5;
        unsigned* as = As + s * GST;
        unsigned* bs = Bs + s * GST;
#pragma unroll
        for (int it = 0; it < 2; it++) {
            int lin = it * 256 + tid;
            int row = lin >> 2, j = lin & 3;
            cp16(&as[row * GSTR + j * 4], A  + (size_t)(m0 + row) * K + k0 + j * 8);
            cp16(&bs[row * GSTR + j * 4], Bt + (size_t)(n0 + row) * K + k0 + j * 8);
        }
        CP_COMMIT();
    };

    float acc[2][8][4];
#pragma unroll
    for (int i = 0; i < 2; i++)
#pragma unroll
        for (int j = 0; j < 8; j++)
#pragma unroll
            for (int t = 0; t < 4; t++) acc[i][j][t] = 0.f;

    fill(0, 0);
    fill(1, 1);

    for (int kt = 0; kt < nk; kt++) {
        CP_WAIT1();
        __syncthreads();
        if (kt + 2 < nk) fill(kt + 2, (kt + 2) % 3);
        else CP_COMMIT();

        const uint32_t as = as_base + (uint32_t)((kt % 3) * GST * 4);
        const uint32_t bs = bs_base + (uint32_t)((kt % 3) * GST * 4);
#pragma unroll
        for (int kc = 0; kc < 2; kc++) {
            unsigned af[2][4], bf[8][2];
#pragma unroll
            for (int mt = 0; mt < 2; mt++)
                ldm_x4(af[mt][0], af[mt][1], af[mt][2], af[mt][3],
                       as + (uint32_t)(((wm + mt * 16 + a_row) * GSTR + kc * 8 + a_k) * 4));
#pragma unroll
            for (int np = 0; np < 4; np++)
                ldm_x4(bf[2 * np][0], bf[2 * np][1], bf[2 * np + 1][0], bf[2 * np + 1][1],
                       bs + (uint32_t)(((wn + np * 16 + b_row) * GSTR + kc * 8 + b_k) * 4));
#pragma unroll
            for (int mt = 0; mt < 2; mt++)
#pragma unroll
                for (int nt = 0; nt < 8; nt++)
                    mma_f16(acc[mt][nt], af[mt][0], af[mt][1], af[mt][2], af[mt][3],
                            bf[nt][0], bf[nt][1]);
        }
    }

#pragma unroll
    for (int mt = 0; mt < 2; mt++) {
#pragma unroll
        for (int nt = 0; nt < 8; nt++) {
            int n = n0 + wn + nt * 8 + 2 * tig;
            float2 bb = *reinterpret_cast<const float2*>(&bias[n]);
            int m = m0 + wm + mt * 16 + gid;
            float v00 = acc[mt][nt][0] + bb.x, v01 = acc[mt][nt][1] + bb.y;
            float v10 = acc[mt][nt][2] + bb.x, v11 = acc[mt][nt][3] + bb.y;
            if (OUT_HALF) {
                __half* C = (__half*)Cv;
                *reinterpret_cast<__half2*>(&C[(size_t)m * N + n])       = __floats2half2_rn(v00, v01);
                *reinterpret_cast<__half2*>(&C[(size_t)(m + 8) * N + n]) = __floats2half2_rn(v10, v11);
            } else {
                float* C = (float*)Cv;
                *reinterpret_cast<float2*>(&C[(size_t)m * N + n])       = make_float2(v00, v01);
                *reinterpret_cast<float2*>(&C[(size_t)(m + 8) * N + n]) = make_float2(v10, v11);
            }
        }
    }
}

// ---------------------------------------------------------------------------
// Fused attention (fp16): q-tile 128, 64-key chunks, 3-stage cp.async,
// one sync/iter. Score K-frags AND V-frags via ldmatrix. attn fp32 out.
// ---------------------------------------------------------------------------
#define KSTR 36                            // u32 per row (32 data + 4 pad)
#define KCH  64
#define KSTG (KCH * KSTR)                  // 2304 words
#define ATTN_SMEM (3 * 2 * KSTG * 4)       // 55296 B

__global__ void __launch_bounds__(256, 2) fused_attn(float* __restrict__ attn)
{
    extern __shared__ unsigned sm[];
    unsigned* KsB = sm;
    unsigned* VsB = sm + 3 * KSTG;
    const uint32_t ks_base = smem_u32(KsB);
    const uint32_t vs_base = smem_u32(VsB);

    const int z  = blockIdx.y;
    const int b  = z >> 4;
    const int h  = z & 15;
    const int m0 = blockIdx.x * 128;

    const __half* Qb = g_qkvh + (size_t)b * TT * D3 + h * 192;
    const __half* Kb = Qb + 64;
    const __half* Vb = Qb + 128;
    float* S = attn + (size_t)z * TT * TT;

    const int tid = threadIdx.x;
    const int w   = tid >> 5;
    const int ln  = tid & 31;
    const int gid = ln >> 2;
    const int tig = ln & 3;
    const int wm  = w * 16;

    // ldmatrix address components (K-tile B-frags: nt pair x k-octet)
    const int b_row = (ln & 7) + (ln >> 4) * 8;
    const int b_k   = ((ln >> 3) & 1) * 4;

    auto issueK = [&](int ck, int s) {
#pragma unroll
        for (int it = 0; it < 2; it++) {
            int lin = it * 256 + tid;
            int row = lin >> 3, j = lin & 7;
            cp16(&KsB[s * KSTG + row * KSTR + j * 4],
                 Kb + (size_t)(ck * KCH + row) * D3 + j * 8);
        }
        CP_COMMIT();
    };
    auto issueKV = [&](int ck, int s) {
#pragma unroll
        for (int it = 0; it < 2; it++) {
            int lin = it * 256 + tid;
            int row = lin >> 3, j = lin & 7;
            cp16(&KsB[s * KSTG + row * KSTR + j * 4],
                 Kb + (size_t)(ck * KCH + row) * D3 + j * 8);
            cp16(&VsB[s * KSTG + row * KSTR + j * 4],
                 Vb + (size_t)(ck * KCH + row) * D3 + j * 8);
        }
        CP_COMMIT();
    };

    // ---- stage Q into K stages 0/1, extract per-warp A fragments
    {
#pragma unroll
        for (int it = 0; it < 4; it++) {
            int lin = it * 256 + tid;
            int row = lin >> 3, j = lin & 7;
            unsigned* dst = KsB + (row >> 6) * KSTG + (row & 63) * KSTR + j * 4;
            *reinterpret_cast<uint4*>(dst) =
                *(reinterpret_cast<const uint4*>(Qb + (size_t)(m0 + row) * D3) + j);
        }
    }
    __syncthreads();
    unsigned qf[4][4];
    {
        const int a_row = (ln & 7) + ((ln >> 3) & 1) * 8;
        const int a_k   = (ln >> 4) * 4;
        const uint32_t qbase = ks_base + (uint32_t)((wm >> 6) * KSTG * 4);
        const int qr = (wm & 63) + a_row;
#pragma unroll
        for (int kc = 0; kc < 4; kc++)
            ldm_x4(qf[kc][0], qf[kc][1], qf[kc][2], qf[kc][3],
                   qbase + (uint32_t)((qr * KSTR + kc * 8 + a_k) * 4));
    }
    __syncthreads();

    // ---- pass 1: rowsums of exp(s/8)
    issueK(0, 0);
    issueK(1, 1);

    float rsum0 = 0.f, rsum1 = 0.f;
    for (int ck = 0; ck < 32; ck++) {
        CP_WAIT1();
        __syncthreads();
        if (ck + 2 < 32) issueK(ck + 2, (ck + 2) % 3);
        else CP_COMMIT();

        const uint32_t ks = ks_base + (uint32_t)((ck % 3) * KSTG * 4);
#pragma unroll
        for (int np = 0; np < 4; np++) {
            float s0[4] = {0.f, 0.f, 0.f, 0.f};
            float s1[4] = {0.f, 0.f, 0.f, 0.f};
#pragma unroll
            for (int kc = 0; kc < 4; kc++) {
                unsigned b00, b01, b10, b11;
                ldm_x4(b00, b01, b10, b11,
                       ks + (uint32_t)(((np * 16 + b_row) * KSTR + kc * 8 + b_k) * 4));
                mma_f16(s0, qf[kc][0], qf[kc][1], qf[kc][2], qf[kc][3], b00, b01);
                mma_f16(s1, qf[kc][0], qf[kc][1], qf[kc][2], qf[kc][3], b10, b11);
            }
            rsum0 += __expf(s0[0] * 0.125f) + __expf(s0[1] * 0.125f)
                   + __expf(s1[0] * 0.125f) + __expf(s1[1] * 0.125f);
            rsum1 += __expf(s0[2] * 0.125f) + __expf(s0[3] * 0.125f)
                   + __expf(s1[2] * 0.125f) + __expf(s1[3] * 0.125f);
        }
    }
    rsum0 += __shfl_xor_sync(0xffffffffu, rsum0, 1);
    rsum0 += __shfl_xor_sync(0xffffffffu, rsum0, 2);
    rsum1 += __shfl_xor_sync(0xffffffffu, rsum1, 1);
    rsum1 += __shfl_xor_sync(0xffffffffu, rsum1, 2);
    const float inv0 = 1.0f / rsum0;
    const float inv1 = 1.0f / rsum1;

    __syncthreads();

    // ---- pass 2
    float oacc[8][4];
#pragma unroll
    for (int dt = 0; dt < 8; dt++)
#pragma unroll
        for (int t = 0; t < 4; t++) oacc[dt][t] = 0.f;

    issueKV(0, 0);
    issueKV(1, 1);

    float* Sr0 = S + (size_t)(m0 + wm + gid) * TT + 2 * tig;
    float* Sr1 = S + (size_t)(m0 + wm + gid + 8) * TT + 2 * tig;

    // V ldmatrix.x4.trans address pieces (within a V stage)
    const int li   = ln >> 3;
    const int lsub = ln & 7;
    const uint32_t ldm_off = (uint32_t)(((li & 1) * 8 + lsub) * (KSTR * 4) + ((li >> 1) * 8) * 2);

    for (int ck = 0; ck < 32; ck++) {
        CP_WAIT1();
        __syncthreads();
        if (ck + 2 < 32) issueKV(ck + 2, (ck + 2) % 3);
        else CP_COMMIT();

        const uint32_t ks = ks_base + (uint32_t)((ck % 3) * KSTG * 4);
        const uint32_t vstage = vs_base + (uint32_t)((ck % 3) * KSTG * 4);

#pragma unroll
        for (int j = 0; j < 4; j++) {      // 16 keys per j (one nt pair)
            float s0[4] = {0.f, 0.f, 0.f, 0.f};
            float s1[4] = {0.f, 0.f, 0.f, 0.f};
#pragma unroll
            for (int kc = 0; kc < 4; kc++) {
                unsigned b00, b01, b10, b11;
                ldm_x4(b00, b01, b10, b11,
                       ks + (uint32_t)(((j * 16 + b_row) * KSTR + kc * 8 + b_k) * 4));
                mma_f16(s0, qf[kc][0], qf[kc][1], qf[kc][2], qf[kc][3], b00, b01);
                mma_f16(s1, qf[kc][0], qf[kc][1], qf[kc][2], qf[kc][3], b10, b11);
            }
            float p00 = __expf(s0[0] * 0.125f) * inv0;
            float p01 = __expf(s0[1] * 0.125f) * inv0;
            float p02 = __expf(s0[2] * 0.125f) * inv1;
            float p03 = __expf(s0[3] * 0.125f) * inv1;
            float p10 = __expf(s1[0] * 0.125f) * inv0;
            float p11 = __expf(s1[1] * 0.125f) * inv0;
            float p12 = __expf(s1[2] * 0.125f) * inv1;
            float p13 = __expf(s1[3] * 0.125f) * inv1;

            *reinterpret_cast<float2*>(Sr0 + ck * KCH + (2 * j) * 8)     = make_float2(p00, p01);
            *reinterpret_cast<float2*>(Sr1 + ck * KCH + (2 * j) * 8)     = make_float2(p02, p03);
            *reinterpret_cast<float2*>(Sr0 + ck * KCH + (2 * j + 1) * 8) = make_float2(p10, p11);
            *reinterpret_cast<float2*>(Sr1 + ck * KCH + (2 * j + 1) * 8) = make_float2(p12, p13);

            unsigned a0 = pack_h2(p00, p01);
            unsigned a1 = pack_h2(p02, p03);
            unsigned a2 = pack_h2(p10, p11);
            unsigned a3 = pack_h2(p12, p13);

            const uint32_t kbase = vstage + (uint32_t)(j * 16 * (KSTR * 4)) + ldm_off;
#pragma unroll
            for (int dtp = 0; dtp < 4; dtp++) {
                unsigned r0, r1, r2, r3;
                asm volatile(
                    "ldmatrix.sync.aligned.m8n8.x4.trans.shared.b16 {%0,%1,%2,%3}, [%4];"
                    : "=r"(r0), "=r"(r1), "=r"(r2), "=r"(r3)
                    : "r"(kbase + (uint32_t)(dtp * 32)));
                mma_f16(oacc[2 * dtp],     a0, a1, a2, a3, r0, r1);
                mma_f16(oacc[2 * dtp + 1], a0, a1, a2, a3, r2, r3);
            }
        }
    }

    // ---- epilogue
    __half* Ob = g_valsh + (size_t)b * TT * DD + h * 64;
#pragma unroll
    for (int dt = 0; dt < 8; dt++) {
        *reinterpret_cast<__half2*>(Ob + (size_t)(m0 + wm + gid) * DD + dt * 8 + 2 * tig) =
            __floats2half2_rn(oacc[dt][0], oacc[dt][1]);
        *reinterpret_cast<__half2*>(Ob + (size_t)(m0 + wm + gid + 8) * DD + dt * 8 + 2 * tig) =
            __floats2half2_rn(oacc[dt][2], oacc[dt][3]);
    }
}

// ---------------------------------------------------------------------------
extern "C" void kernel_launch(void* const* d_in, const int* in_sizes, int n_in,
                              void* d_out, int out_size)
{
    const float* x      = (const float*)d_in[0];
    const float* W_qkv  = (const float*)d_in[1];
    const float* b_qkv  = (const float*)d_in[2];
    const float* W_out  = (const float*)d_in[3];
    const float* b_out  = (const float*)d_in[4];

    float* out  = (float*)d_out;
    float* attn = out + (size_t)BB * TT * DD;

    static __half *xh = nullptr, *wqkvh = nullptr, *wouth = nullptr,
                  *qkvh = nullptr, *valsh = nullptr;
    static bool inited = false;
    if (!inited) {
        cudaGetSymbolAddress((void**)&xh, g_xh);
        cudaGetSymbolAddress((void**)&wqkvh, g_wqkvh);
        cudaGetSymbolAddress((void**)&wouth, g_wouth);
        cudaGetSymbolAddress((void**)&qkvh, g_qkvh);
        cudaGetSymbolAddress((void**)&valsh, g_valsh);
        cudaFuncSetAttribute(fused_attn, cudaFuncAttributeMaxDynamicSharedMemorySize, ATTN_SMEM);
        cudaFuncSetAttribute(fused_attn, cudaFuncAttributePreferredSharedMemoryCarveout, 100);
        cudaFuncSetAttribute(gemm_f16<true>,  cudaFuncAttributeMaxDynamicSharedMemorySize, GEMM_SMEM);
        cudaFuncSetAttribute(gemm_f16<true>,  cudaFuncAttributePreferredSharedMemoryCarveout, 100);
        cudaFuncSetAttribute(gemm_f16<false>, cudaFuncAttributeMaxDynamicSharedMemorySize, GEMM_SMEM);
        cudaFuncSetAttribute(gemm_f16<false>, cudaFuncAttributePreferredSharedMemoryCarveout, 100);
        inited = true;
    }

    // 0) Prep: x -> fp16; weights -> transposed fp16
    {
        int n4x = (BB * TT * DD) / 4;
        round_f16_kernel<<<(n4x + 255) / 256, 256>>>((const float4*)x, (__half2*)xh, n4x);
        transpose_f16_kernel<<<dim3(D3 / 32, DD / 32), dim3(32, 8)>>>(W_qkv, wqkvh, DD, D3);
        transpose_f16_kernel<<<dim3(DD / 32, DD / 32), dim3(32, 8)>>>(W_out, wouth, DD, DD);
    }

    // 1) QKV projection (fp16 in, fp16 out)
    gemm_f16<true><<<dim3(D3 / 128, (BB * TT) / 128), 256, GEMM_SMEM>>>(
        xh, wqkvh, b_qkv, qkvh, BB * TT, D3, DD);

    // 2) Fused scores + softmax + AV
    fused_attn<<<dim3(TT / 128, BB * HH), 256, ATTN_SMEM>>>(attn);

    // 3) Output projection (fp16 in, fp32 out)
    gemm_f16<false><<<dim3(DD / 128, (BB * TT) / 128), 256, GEMM_SMEM>>>(
        valsh, wouth, b_out, out, BB * TT, DD, DD);
}

// round 11
// speedup vs baseline: 2.1772x; 1.0370x over previous
#include <cuda_runtime.h>
#include <cuda_fp16.h>
#include <cstdint>

// Problem constants
#define BB  2
#define TT  2048
#define DD  1024
#define HH  16
#define D3  3072   // 3*D

// Scratch (allocation-free rule: __device__ globals), all 16B-aligned
__device__ __align__(16) __half g_xh  [(size_t)BB * TT * DD];
__device__ __align__(16) __half g_wqkvh[(size_t)D3 * DD];       // W_qkv^T [3072][1024]
__device__ __align__(16) __half g_wouth[(size_t)DD * DD];       // W_out^T [1024][1024]
__device__ __align__(16) __half g_qkvh[(size_t)BB * TT * D3];
__device__ __align__(16) __half g_valsh[(size_t)BB * TT * DD];

// ---------------------------------------------------------------------------
// helpers
// ---------------------------------------------------------------------------
__device__ __forceinline__ void mma_f16(float c[4],
                                        unsigned a0, unsigned a1, unsigned a2, unsigned a3,
                                        unsigned b0, unsigned b1) {
    asm volatile(
        "mma.sync.aligned.m16n8k16.row.col.f32.f16.f16.f32 "
        "{%0,%1,%2,%3}, {%4,%5,%6,%7}, {%8,%9}, {%0,%1,%2,%3};"
        : "+f"(c[0]), "+f"(c[1]), "+f"(c[2]), "+f"(c[3])
        : "r"(a0), "r"(a1), "r"(a2), "r"(a3), "r"(b0), "r"(b1));
}

__device__ __forceinline__ void ldm_x4(unsigned& r0, unsigned& r1, unsigned& r2, unsigned& r3,
                                       uint32_t addr) {
    asm volatile("ldmatrix.sync.aligned.m8n8.x4.shared.b16 {%0,%1,%2,%3}, [%4];"
                 : "=r"(r0), "=r"(r1), "=r"(r2), "=r"(r3) : "r"(addr));
}

__device__ __forceinline__ void cp16(unsigned* smem_dst, const void* gsrc) {
    unsigned s = (unsigned)__cvta_generic_to_shared(smem_dst);
    asm volatile("cp.async.cg.shared.global [%0], [%1], 16;" :: "r"(s), "l"(gsrc));
}
#define CP_COMMIT() asm volatile("cp.async.commit_group;")
#define CP_WAIT1()  asm volatile("cp.async.wait_group 1;")

__device__ __forceinline__ uint32_t smem_u32(const void* p) {
    uint32_t a;
    asm("{ .reg .u64 t; cvta.to.shared.u64 t, %1; cvt.u32.u64 %0, t; }" : "=r"(a) : "l"(p));
    return a;
}

__device__ __forceinline__ unsigned pack_h2(float lo, float hi) {
    __half2 h = __floats2half2_rn(lo, hi);
    return *reinterpret_cast<unsigned*>(&h);
}

__device__ __forceinline__ void stcs_f2(float* p, float a, float b) {
    asm volatile("st.global.cs.v2.f32 [%0], {%1,%2};" :: "l"(p), "f"(a), "f"(b) : "memory");
}

// ---------------------------------------------------------------------------
// Prep kernels
// ---------------------------------------------------------------------------
__global__ void round_f16_kernel(const float4* __restrict__ in,
                                 __half2* __restrict__ out, int n4)
{
    int i = blockIdx.x * blockDim.x + threadIdx.x;
    if (i < n4) {
        float4 v = in[i];
        out[2 * i]     = __floats2half2_rn(v.x, v.y);
        out[2 * i + 1] = __floats2half2_rn(v.z, v.w);
    }
}

__global__ void transpose_f16_kernel(const float* __restrict__ in,
                                     __half* __restrict__ out, int K, int N)
{
    __shared__ float t[32][33];
    const int bx = blockIdx.x * 32;   // n
    const int by = blockIdx.y * 32;   // k
    const int x = threadIdx.x, y = threadIdx.y;
#pragma unroll
    for (int i = 0; i < 32; i += 8)
        t[y + i][x] = in[(size_t)(by + y + i) * N + bx + x];
    __syncthreads();
#pragma unroll
    for (int i = 0; i < 32; i += 8)
        out[(size_t)(bx + y + i) * K + by + x] = __float2half_rn(t[x][y + i]);
}

// ---------------------------------------------------------------------------
// fp16 NT GEMM + bias: C[M,N] = A[M,K] @ Bt[N,K]^T + bias[N].
// BM=128, BN=128, BK=64 halves (128B rows). 256 threads, 3-stage cp.async,
// ONE __syncthreads per 64-deep k-step (16 total). ldmatrix fragments.
// ---------------------------------------------------------------------------
#define GSTR 36                          // u32 stride per row (32 data + 4 pad)
#define GST  (128 * GSTR)                // 4608 u32 per tile
#define GEMM_SMEM (3 * 2 * GST * 4)      // 110592 B

template <bool OUT_HALF>
__global__ void __launch_bounds__(256, 2) gemm_f16(
    const __half* __restrict__ A, const __half* __restrict__ Bt,
    const float* __restrict__ bias, void* __restrict__ Cv,
    int M, int N, int K)
{
    extern __shared__ unsigned gsm[];
    unsigned* As = gsm;
    unsigned* Bs = gsm + 3 * GST;
    const uint32_t as_base = smem_u32(As);
    const uint32_t bs_base = smem_u32(Bs);

    const int tid = threadIdx.x;
    const int w   = tid >> 5;
    const int ln  = tid & 31;
    const int gid = ln >> 2;
    const int tig = ln & 3;
    const int wm  = (w & 3) * 32;
    const int wn  = (w >> 2) * 64;
    const int m0  = blockIdx.y * 128;
    const int n0  = blockIdx.x * 128;

    // ldmatrix per-thread address components
    const int a_row = (ln & 7) + ((ln >> 3) & 1) * 8;     // 0..15
    const int a_k   = (ln >> 4) * 4;                      // 0 or 4 (u32)
    const int b_row = (ln & 7) + (ln >> 4) * 8;           // 0..15
    const int b_k   = ((ln >> 3) & 1) * 4;                // 0 or 4 (u32)

    const int nk = K >> 6;               // BK = 64 halves

    auto fill = [&](int kt, int s) {
        int k0 = kt << 6;
        unsigned* as = As + s * GST;
        unsigned* bs = Bs + s * GST;
#pragma unroll
        for (int it = 0; it < 4; it++) {
            int lin = it * 256 + tid;
            int row = lin >> 3, j = lin & 7;       // 8 x 16B per 128B row
            cp16(&as[row * GSTR + j * 4], A  + (size_t)(m0 + row) * K + k0 + j * 8);
            cp16(&bs[row * GSTR + j * 4], Bt + (size_t)(n0 + row) * K + k0 + j * 8);
        }
        CP_COMMIT();
    };

    float acc[2][8][4];
#pragma unroll
    for (int i = 0; i < 2; i++)
#pragma unroll
        for (int j = 0; j < 8; j++)
#pragma unroll
            for (int t = 0; t < 4; t++) acc[i][j][t] = 0.f;

    fill(0, 0);
    fill(1, 1);

    for (int kt = 0; kt < nk; kt++) {
        CP_WAIT1();
        __syncthreads();
        if (kt + 2 < nk) fill(kt + 2, (kt + 2) % 3);
        else CP_COMMIT();

        const uint32_t as = as_base + (uint32_t)((kt % 3) * GST * 4);
        const uint32_t bs = bs_base + (uint32_t)((kt % 3) * GST * 4);
#pragma unroll
        for (int kc = 0; kc < 4; kc++) {          // 4 x k16 per BK=64
            unsigned af[2][4], bf[8][2];
#pragma unroll
            for (int mt = 0; mt < 2; mt++)
                ldm_x4(af[mt][0], af[mt][1], af[mt][2], af[mt][3],
                       as + (uint32_t)(((wm + mt * 16 + a_row) * GSTR + kc * 8 + a_k) * 4));
#pragma unroll
            for (int np = 0; np < 4; np++)
                ldm_x4(bf[2 * np][0], bf[2 * np][1], bf[2 * np + 1][0], bf[2 * np + 1][1],
                       bs + (uint32_t)(((wn + np * 16 + b_row) * GSTR + kc * 8 + b_k) * 4));
#pragma unroll
            for (int mt = 0; mt < 2; mt++)
#pragma unroll
                for (int nt = 0; nt < 8; nt++)
                    mma_f16(acc[mt][nt], af[mt][0], af[mt][1], af[mt][2], af[mt][3],
                            bf[nt][0], bf[nt][1]);
        }
    }

#pragma unroll
    for (int mt = 0; mt < 2; mt++) {
#pragma unroll
        for (int nt = 0; nt < 8; nt++) {
            int n = n0 + wn + nt * 8 + 2 * tig;
            float2 bb = *reinterpret_cast<const float2*>(&bias[n]);
            int m = m0 + wm + mt * 16 + gid;
            float v00 = acc[mt][nt][0] + bb.x, v01 = acc[mt][nt][1] + bb.y;
            float v10 = acc[mt][nt][2] + bb.x, v11 = acc[mt][nt][3] + bb.y;
            if (OUT_HALF) {
                __half* C = (__half*)Cv;
                *reinterpret_cast<__half2*>(&C[(size_t)m * N + n])       = __floats2half2_rn(v00, v01);
                *reinterpret_cast<__half2*>(&C[(size_t)(m + 8) * N + n]) = __floats2half2_rn(v10, v11);
            } else {
                float* C = (float*)Cv;
                *reinterpret_cast<float2*>(&C[(size_t)m * N + n])       = make_float2(v00, v01);
                *reinterpret_cast<float2*>(&C[(size_t)(m + 8) * N + n]) = make_float2(v10, v11);
            }
        }
    }
}

// ---------------------------------------------------------------------------
// Fused attention (fp16): q-tile 128, 64-key chunks, 3-stage cp.async,
// one sync/iter. Score K-frags AND V-frags via ldmatrix. attn stores use
// st.global.cs (streaming; keep L2 for K/V tiles).
// ---------------------------------------------------------------------------
#define KSTR 36                            // u32 per row (32 data + 4 pad)
#define KCH  64
#define KSTG (KCH * KSTR)                  // 2304 words
#define ATTN_SMEM (3 * 2 * KSTG * 4)       // 55296 B

__global__ void __launch_bounds__(256, 2) fused_attn(float* __restrict__ attn)
{
    extern __shared__ unsigned sm[];
    unsigned* KsB = sm;
    unsigned* VsB = sm + 3 * KSTG;
    const uint32_t ks_base = smem_u32(KsB);
    const uint32_t vs_base = smem_u32(VsB);

    const int z  = blockIdx.y;
    const int b  = z >> 4;
    const int h  = z & 15;
    const int m0 = blockIdx.x * 128;

    const __half* Qb = g_qkvh + (size_t)b * TT * D3 + h * 192;
    const __half* Kb = Qb + 64;
    const __half* Vb = Qb + 128;
    float* S = attn + (size_t)z * TT * TT;

    const int tid = threadIdx.x;
    const int w   = tid >> 5;
    const int ln  = tid & 31;
    const int gid = ln >> 2;
    const int tig = ln & 3;
    const int wm  = w * 16;

    const int b_row = (ln & 7) + (ln >> 4) * 8;
    const int b_k   = ((ln >> 3) & 1) * 4;

    auto issueK = [&](int ck, int s) {
#pragma unroll
        for (int it = 0; it < 2; it++) {
            int lin = it * 256 + tid;
            int row = lin >> 3, j = lin & 7;
            cp16(&KsB[s * KSTG + row * KSTR + j * 4],
                 Kb + (size_t)(ck * KCH + row) * D3 + j * 8);
        }
        CP_COMMIT();
    };
    auto issueKV = [&](int ck, int s) {
#pragma unroll
        for (int it = 0; it < 2; it++) {
            int lin = it * 256 + tid;
            int row = lin >> 3, j = lin & 7;
            cp16(&KsB[s * KSTG + row * KSTR + j * 4],
                 Kb + (size_t)(ck * KCH + row) * D3 + j * 8);
            cp16(&VsB[s * KSTG + row * KSTR + j * 4],
                 Vb + (size_t)(ck * KCH + row) * D3 + j * 8);
        }
        CP_COMMIT();
    };

    // ---- stage Q into K stages 0/1, extract per-warp A fragments
    {
#pragma unroll
        for (int it = 0; it < 4; it++) {
            int lin = it * 256 + tid;
            int row = lin >> 3, j = lin & 7;
            unsigned* dst = KsB + (row >> 6) * KSTG + (row & 63) * KSTR + j * 4;
            *reinterpret_cast<uint4*>(dst) =
                *(reinterpret_cast<const uint4*>(Qb + (size_t)(m0 + row) * D3) + j);
        }
    }
    __syncthreads();
    unsigned qf[4][4];
    {
        const int a_row = (ln & 7) + ((ln >> 3) & 1) * 8;
        const int a_k   = (ln >> 4) * 4;
        const uint32_t qbase = ks_base + (uint32_t)((wm >> 6) * KSTG * 4);
        const int qr = (wm & 63) + a_row;
#pragma unroll
        for (int kc = 0; kc < 4; kc++)
            ldm_x4(qf[kc][0], qf[kc][1], qf[kc][2], qf[kc][3],
                   qbase + (uint32_t)((qr * KSTR + kc * 8 + a_k) * 4));
    }
    __syncthreads();

    // ---- pass 1: rowsums of exp(s/8)
    issueK(0, 0);
    issueK(1, 1);

    float rsum0 = 0.f, rsum1 = 0.f;
    for (int ck = 0; ck < 32; ck++) {
        CP_WAIT1();
        __syncthreads();
        if (ck + 2 < 32) issueK(ck + 2, (ck + 2) % 3);
        else CP_COMMIT();

        const uint32_t ks = ks_base + (uint32_t)((ck % 3) * KSTG * 4);
#pragma unroll
        for (int np = 0; np < 4; np++) {
            float s0[4] = {0.f, 0.f, 0.f, 0.f};
            float s1[4] = {0.f, 0.f, 0.f, 0.f};
#pragma unroll
            for (int kc = 0; kc < 4; kc++) {
                unsigned b00, b01, b10, b11;
                ldm_x4(b00, b01, b10, b11,
                       ks + (uint32_t)(((np * 16 + b_row) * KSTR + kc * 8 + b_k) * 4));
                mma_f16(s0, qf[kc][0], qf[kc][1], qf[kc][2], qf[kc][3], b00, b01);
                mma_f16(s1, qf[kc][0], qf[kc][1], qf[kc][2], qf[kc][3], b10, b11);
            }
            rsum0 += __expf(s0[0] * 0.125f) + __expf(s0[1] * 0.125f)
                   + __expf(s1[0] * 0.125f) + __expf(s1[1] * 0.125f);
            rsum1 += __expf(s0[2] * 0.125f) + __expf(s0[3] * 0.125f)
                   + __expf(s1[2] * 0.125f) + __expf(s1[3] * 0.125f);
        }
    }
    rsum0 += __shfl_xor_sync(0xffffffffu, rsum0, 1);
    rsum0 += __shfl_xor_sync(0xffffffffu, rsum0, 2);
    rsum1 += __shfl_xor_sync(0xffffffffu, rsum1, 1);
    rsum1 += __shfl_xor_sync(0xffffffffu, rsum1, 2);
    const float inv0 = 1.0f / rsum0;
    const float inv1 = 1.0f / rsum1;

    __syncthreads();

    // ---- pass 2
    float oacc[8][4];
#pragma unroll
    for (int dt = 0; dt < 8; dt++)
#pragma unroll
        for (int t = 0; t < 4; t++) oacc[dt][t] = 0.f;

    issueKV(0, 0);
    issueKV(1, 1);

    float* Sr0 = S + (size_t)(m0 + wm + gid) * TT + 2 * tig;
    float* Sr1 = S + (size_t)(m0 + wm + gid + 8) * TT + 2 * tig;

    const int li   = ln >> 3;
    const int lsub = ln & 7;
    const uint32_t ldm_off = (uint32_t)(((li & 1) * 8 + lsub) * (KSTR * 4) + ((li >> 1) * 8) * 2);

    for (int ck = 0; ck < 32; ck++) {
        CP_WAIT1();
        __syncthreads();
        if (ck + 2 < 32) issueKV(ck + 2, (ck + 2) % 3);
        else CP_COMMIT();

        const uint32_t ks = ks_base + (uint32_t)((ck % 3) * KSTG * 4);
        const uint32_t vstage = vs_base + (uint32_t)((ck % 3) * KSTG * 4);

#pragma unroll
        for (int j = 0; j < 4; j++) {
            float s0[4] = {0.f, 0.f, 0.f, 0.f};
            float s1[4] = {0.f, 0.f, 0.f, 0.f};
#pragma unroll
            for (int kc = 0; kc < 4; kc++) {
                unsigned b00, b01, b10, b11;
                ldm_x4(b00, b01, b10, b11,
                       ks + (uint32_t)(((j * 16 + b_row) * KSTR + kc * 8 + b_k) * 4));
                mma_f16(s0, qf[kc][0], qf[kc][1], qf[kc][2], qf[kc][3], b00, b01);
                mma_f16(s1, qf[kc][0], qf[kc][1], qf[kc][2], qf[kc][3], b10, b11);
            }
            float p00 = __expf(s0[0] * 0.125f) * inv0;
            float p01 = __expf(s0[1] * 0.125f) * inv0;
            float p02 = __expf(s0[2] * 0.125f) * inv1;
            float p03 = __expf(s0[3] * 0.125f) * inv1;
            float p10 = __expf(s1[0] * 0.125f) * inv0;
            float p11 = __expf(s1[1] * 0.125f) * inv0;
            float p12 = __expf(s1[2] * 0.125f) * inv1;
            float p13 = __expf(s1[3] * 0.125f) * inv1;

            stcs_f2(Sr0 + ck * KCH + (2 * j) * 8,     p00, p01);
            stcs_f2(Sr1 + ck * KCH + (2 * j) * 8,     p02, p03);
            stcs_f2(Sr0 + ck * KCH + (2 * j + 1) * 8, p10, p11);
            stcs_f2(Sr1 + ck * KCH + (2 * j + 1) * 8, p12, p13);

            unsigned a0 = pack_h2(p00, p01);
            unsigned a1 = pack_h2(p02, p03);
            unsigned a2 = pack_h2(p10, p11);
            unsigned a3 = pack_h2(p12, p13);

            const uint32_t kbase = vstage + (uint32_t)(j * 16 * (KSTR * 4)) + ldm_off;
#pragma unroll
            for (int dtp = 0; dtp < 4; dtp++) {
                unsigned r0, r1, r2, r3;
                asm volatile(
                    "ldmatrix.sync.aligned.m8n8.x4.trans.shared.b16 {%0,%1,%2,%3}, [%4];"
                    : "=r"(r0), "=r"(r1), "=r"(r2), "=r"(r3)
                    : "r"(kbase + (uint32_t)(dtp * 32)));
                mma_f16(oacc[2 * dtp],     a0, a1, a2, a3, r0, r1);
                mma_f16(oacc[2 * dtp + 1], a0, a1, a2, a3, r2, r3);
            }
        }
    }

    // ---- epilogue
    __half* Ob = g_valsh + (size_t)b * TT * DD + h * 64;
#pragma unroll
    for (int dt = 0; dt < 8; dt++) {
        *reinterpret_cast<__half2*>(Ob + (size_t)(m0 + wm + gid) * DD + dt * 8 + 2 * tig) =
            __floats2half2_rn(oacc[dt][0], oacc[dt][1]);
        *reinterpret_cast<__half2*>(Ob + (size_t)(m0 + wm + gid + 8) * DD + dt * 8 + 2 * tig) =
            __floats2half2_rn(oacc[dt][2], oacc[dt][3]);
    }
}

// ---------------------------------------------------------------------------
extern "C" void kernel_launch(void* const* d_in, const int* in_sizes, int n_in,
                              void* d_out, int out_size)
{
    const float* x      = (const float*)d_in[0];
    const float* W_qkv  = (const float*)d_in[1];
    const float* b_qkv  = (const float*)d_in[2];
    const float* W_out  = (const float*)d_in[3];
    const float* b_out  = (const float*)d_in[4];

    float* out  = (float*)d_out;
    float* attn = out + (size_t)BB * TT * DD;

    static __half *xh = nullptr, *wqkvh = nullptr, *wouth = nullptr,
                  *qkvh = nullptr, *valsh = nullptr;
    static bool inited = false;
    if (!inited) {
        cudaGetSymbolAddress((void**)&xh, g_xh);
        cudaGetSymbolAddress((void**)&wqkvh, g_wqkvh);
        cudaGetSymbolAddress((void**)&wouth, g_wouth);
        cudaGetSymbolAddress((void**)&qkvh, g_qkvh);
        cudaGetSymbolAddress((void**)&valsh, g_valsh);
        cudaFuncSetAttribute(fused_attn, cudaFuncAttributeMaxDynamicSharedMemorySize, ATTN_SMEM);
        cudaFuncSetAttribute(fused_attn, cudaFuncAttributePreferredSharedMemoryCarveout, 100);
        cudaFuncSetAttribute(gemm_f16<true>,  cudaFuncAttributeMaxDynamicSharedMemorySize, GEMM_SMEM);
        cudaFuncSetAttribute(gemm_f16<true>,  cudaFuncAttributePreferredSharedMemoryCarveout, 100);
        cudaFuncSetAttribute(gemm_f16<false>, cudaFuncAttributeMaxDynamicSharedMemorySize, GEMM_SMEM);
        cudaFuncSetAttribute(gemm_f16<false>, cudaFuncAttributePreferredSharedMemoryCarveout, 100);
        inited = true;
    }

    // 0) Prep: x -> fp16; weights -> transposed fp16
    {
        int n4x = (BB * TT * DD) / 4;
        round_f16_kernel<<<(n4x + 255) / 256, 256>>>((const float4*)x, (__half2*)xh, n4x);
        transpose_f16_kernel<<<dim3(D3 / 32, DD / 32), dim3(32, 8)>>>(W_qkv, wqkvh, DD, D3);
        transpose_f16_kernel<<<dim3(DD / 32, DD / 32), dim3(32, 8)>>>(W_out, wouth, DD, DD);
    }

    // 1) QKV projection (fp16 in, fp16 out)
    gemm_f16<true><<<dim3(D3 / 128, (BB * TT) / 128), 256, GEMM_SMEM>>>(
        xh, wqkvh, b_qkv, qkvh, BB * TT, D3, DD);

    // 2) Fused scores + softmax + AV
    fused_attn<<<dim3(TT / 128, BB * HH), 256, ATTN_SMEM>>>(attn);

    // 3) Output projection (fp16 in, fp32 out)
    gemm_f16<false><<<dim3(DD / 128, (BB * TT) / 128), 256, GEMM_SMEM>>>(
        valsh, wouth, b_out, out, BB * TT, DD, DD);
}

// round 12
// speedup vs baseline: 2.2128x; 1.0164x over previous
#include <cuda_runtime.h>
#include <cuda_fp16.h>
#include <cstdint>

// Problem constants
#define BB  2
#define TT  2048
#define DD  1024
#define HH  16
#define D3  3072   // 3*D

// Scratch (allocation-free rule: __device__ globals), all 16B-aligned
__device__ __align__(16) __half g_xh  [(size_t)BB * TT * DD];
__device__ __align__(16) __half g_wqkvh[(size_t)D3 * DD];       // W_qkv^T [3072][1024]
__device__ __align__(16) __half g_wouth[(size_t)DD * DD];       // W_out^T [1024][1024]
__device__ __align__(16) __half g_qkvh[(size_t)BB * TT * D3];   // Q pre-scaled by 0.125*log2e
__device__ __align__(16) __half g_valsh[(size_t)BB * TT * DD];

#define QSCALE 0.18033688011112042f   // 0.125 * log2(e)

// ---------------------------------------------------------------------------
// helpers
// ---------------------------------------------------------------------------
__device__ __forceinline__ void mma_f16(float c[4],
                                        unsigned a0, unsigned a1, unsigned a2, unsigned a3,
                                        unsigned b0, unsigned b1) {
    asm volatile(
        "mma.sync.aligned.m16n8k16.row.col.f32.f16.f16.f32 "
        "{%0,%1,%2,%3}, {%4,%5,%6,%7}, {%8,%9}, {%0,%1,%2,%3};"
        : "+f"(c[0]), "+f"(c[1]), "+f"(c[2]), "+f"(c[3])
        : "r"(a0), "r"(a1), "r"(a2), "r"(a3), "r"(b0), "r"(b1));
}

__device__ __forceinline__ void ldm_x4(unsigned& r0, unsigned& r1, unsigned& r2, unsigned& r3,
                                       uint32_t addr) {
    asm volatile("ldmatrix.sync.aligned.m8n8.x4.shared.b16 {%0,%1,%2,%3}, [%4];"
                 : "=r"(r0), "=r"(r1), "=r"(r2), "=r"(r3) : "r"(addr));
}

__device__ __forceinline__ void cp16(unsigned* smem_dst, const void* gsrc) {
    unsigned s = (unsigned)__cvta_generic_to_shared(smem_dst);
    asm volatile("cp.async.cg.shared.global [%0], [%1], 16;" :: "r"(s), "l"(gsrc));
}
#define CP_COMMIT() asm volatile("cp.async.commit_group;")
#define CP_WAIT1()  asm volatile("cp.async.wait_group 1;")

__device__ __forceinline__ uint32_t smem_u32(const void* p) {
    uint32_t a;
    asm("{ .reg .u64 t; cvta.to.shared.u64 t, %1; cvt.u32.u64 %0, t; }" : "=r"(a) : "l"(p));
    return a;
}

__device__ __forceinline__ unsigned pack_h2(float lo, float hi) {
    __half2 h = __floats2half2_rn(lo, hi);
    return *reinterpret_cast<unsigned*>(&h);
}

__device__ __forceinline__ void stcs_f2(float* p, float a, float b) {
    asm volatile("st.global.cs.v2.f32 [%0], {%1,%2};" :: "l"(p), "f"(a), "f"(b) : "memory");
}

// ---------------------------------------------------------------------------
// Prep kernels
// ---------------------------------------------------------------------------
__global__ void round_f16_kernel(const float4* __restrict__ in,
                                 __half2* __restrict__ out, int n4)
{
    int i = blockIdx.x * blockDim.x + threadIdx.x;
    if (i < n4) {
        float4 v = in[i];
        out[2 * i]     = __floats2half2_rn(v.x, v.y);
        out[2 * i + 1] = __floats2half2_rn(v.z, v.w);
    }
}

__global__ void transpose_f16_kernel(const float* __restrict__ in,
                                     __half* __restrict__ out, int K, int N)
{
    __shared__ float t[32][33];
    const int bx = blockIdx.x * 32;   // n
    const int by = blockIdx.y * 32;   // k
    const int x = threadIdx.x, y = threadIdx.y;
#pragma unroll
    for (int i = 0; i < 32; i += 8)
        t[y + i][x] = in[(size_t)(by + y + i) * N + bx + x];
    __syncthreads();
#pragma unroll
    for (int i = 0; i < 32; i += 8)
        out[(size_t)(bx + y + i) * K + by + x] = __float2half_rn(t[x][y + i]);
}

// ---------------------------------------------------------------------------
// fp16 NT GEMM + bias: C[M,N] = A[M,K] @ Bt[N,K]^T + bias[N].
// BM=128, BN=128, BK=64 halves. 256 threads, 3-stage cp.async, 1 sync/iter.
// SCALE_Q: multiply Q columns (n%192 < 64) by QSCALE in fp32 before rounding.
// ---------------------------------------------------------------------------
#define GSTR 36                          // u32 stride per row (32 data + 4 pad)
#define GST  (128 * GSTR)
#define GEMM_SMEM (3 * 2 * GST * 4)      // 110592 B

template <bool OUT_HALF, bool SCALE_Q>
__global__ void __launch_bounds__(256, 2) gemm_f16(
    const __half* __restrict__ A, const __half* __restrict__ Bt,
    const float* __restrict__ bias, void* __restrict__ Cv,
    int M, int N, int K)
{
    extern __shared__ unsigned gsm[];
    unsigned* As = gsm;
    unsigned* Bs = gsm + 3 * GST;
    const uint32_t as_base = smem_u32(As);
    const uint32_t bs_base = smem_u32(Bs);

    const int tid = threadIdx.x;
    const int w   = tid >> 5;
    const int ln  = tid & 31;
    const int gid = ln >> 2;
    const int tig = ln & 3;
    const int wm  = (w & 3) * 32;
    const int wn  = (w >> 2) * 64;
    const int m0  = blockIdx.y * 128;
    const int n0  = blockIdx.x * 128;

    const int a_row = (ln & 7) + ((ln >> 3) & 1) * 8;
    const int a_k   = (ln >> 4) * 4;
    const int b_row = (ln & 7) + (ln >> 4) * 8;
    const int b_k   = ((ln >> 3) & 1) * 4;

    const int nk = K >> 6;

    auto fill = [&](int kt, int s) {
        int k0 = kt << 6;
        unsigned* as = As + s * GST;
        unsigned* bs = Bs + s * GST;
#pragma unroll
        for (int it = 0; it < 4; it++) {
            int lin = it * 256 + tid;
            int row = lin >> 3, j = lin & 7;
            cp16(&as[row * GSTR + j * 4], A  + (size_t)(m0 + row) * K + k0 + j * 8);
            cp16(&bs[row * GSTR + j * 4], Bt + (size_t)(n0 + row) * K + k0 + j * 8);
        }
        CP_COMMIT();
    };

    float acc[2][8][4];
#pragma unroll
    for (int i = 0; i < 2; i++)
#pragma unroll
        for (int j = 0; j < 8; j++)
#pragma unroll
            for (int t = 0; t < 4; t++) acc[i][j][t] = 0.f;

    fill(0, 0);
    fill(1, 1);

    for (int kt = 0; kt < nk; kt++) {
        CP_WAIT1();
        __syncthreads();
        if (kt + 2 < nk) fill(kt + 2, (kt + 2) % 3);
        else CP_COMMIT();

        const uint32_t as = as_base + (uint32_t)((kt % 3) * GST * 4);
        const uint32_t bs = bs_base + (uint32_t)((kt % 3) * GST * 4);
#pragma unroll
        for (int kc = 0; kc < 4; kc++) {
            unsigned af[2][4], bf[8][2];
#pragma unroll
            for (int mt = 0; mt < 2; mt++)
                ldm_x4(af[mt][0], af[mt][1], af[mt][2], af[mt][3],
                       as + (uint32_t)(((wm + mt * 16 + a_row) * GSTR + kc * 8 + a_k) * 4));
#pragma unroll
            for (int np = 0; np < 4; np++)
                ldm_x4(bf[2 * np][0], bf[2 * np][1], bf[2 * np + 1][0], bf[2 * np + 1][1],
                       bs + (uint32_t)(((wn + np * 16 + b_row) * GSTR + kc * 8 + b_k) * 4));
#pragma unroll
            for (int mt = 0; mt < 2; mt++)
#pragma unroll
                for (int nt = 0; nt < 8; nt++)
                    mma_f16(acc[mt][nt], af[mt][0], af[mt][1], af[mt][2], af[mt][3],
                            bf[nt][0], bf[nt][1]);
        }
    }

#pragma unroll
    for (int mt = 0; mt < 2; mt++) {
#pragma unroll
        for (int nt = 0; nt < 8; nt++) {
            int n = n0 + wn + nt * 8 + 2 * tig;
            float2 bb = *reinterpret_cast<const float2*>(&bias[n]);
            int m = m0 + wm + mt * 16 + gid;
            float v00 = acc[mt][nt][0] + bb.x, v01 = acc[mt][nt][1] + bb.y;
            float v10 = acc[mt][nt][2] + bb.x, v11 = acc[mt][nt][3] + bb.y;
            if (SCALE_Q) {
                if ((n % 192) < 64) {   // Q columns: fold softmax scale (fp32, exact path)
                    v00 *= QSCALE; v01 *= QSCALE; v10 *= QSCALE; v11 *= QSCALE;
                }
            }
            if (OUT_HALF) {
                __half* C = (__half*)Cv;
                *reinterpret_cast<__half2*>(&C[(size_t)m * N + n])       = __floats2half2_rn(v00, v01);
                *reinterpret_cast<__half2*>(&C[(size_t)(m + 8) * N + n]) = __floats2half2_rn(v10, v11);
            } else {
                float* C = (float*)Cv;
                *reinterpret_cast<float2*>(&C[(size_t)m * N + n])       = make_float2(v00, v01);
                *reinterpret_cast<float2*>(&C[(size_t)(m + 8) * N + n]) = make_float2(v10, v11);
            }
        }
    }
}

// ---------------------------------------------------------------------------
// Fused attention (fp16): q-tile 128, 128-key chunks (16 iters/pass),
// 3-stage cp.async, one sync/iter. Q is pre-scaled so p = exp2f(s) directly.
// attn stores streaming (st.global.cs).
// ---------------------------------------------------------------------------
#define KSTR 36                            // u32 per row (32 data + 4 pad)
#define KCH  128
#define KSTG (KCH * KSTR)                  // 4608 words (18 KB)
#define ATTN_SMEM (3 * 2 * KSTG * 4)       // 110592 B

__global__ void __launch_bounds__(256, 2) fused_attn(float* __restrict__ attn)
{
    extern __shared__ unsigned sm[];
    unsigned* KsB = sm;
    unsigned* VsB = sm + 3 * KSTG;
    const uint32_t ks_base = smem_u32(KsB);
    const uint32_t vs_base = smem_u32(VsB);

    const int z  = blockIdx.y;
    const int b  = z >> 4;
    const int h  = z & 15;
    const int m0 = blockIdx.x * 128;

    const __half* Qb = g_qkvh + (size_t)b * TT * D3 + h * 192;
    const __half* Kb = Qb + 64;
    const __half* Vb = Qb + 128;
    float* S = attn + (size_t)z * TT * TT;

    const int tid = threadIdx.x;
    const int w   = tid >> 5;
    const int ln  = tid & 31;
    const int gid = ln >> 2;
    const int tig = ln & 3;
    const int wm  = w * 16;

    const int b_row = (ln & 7) + (ln >> 4) * 8;
    const int b_k   = ((ln >> 3) & 1) * 4;

    auto issueK = [&](int ck, int s) {
#pragma unroll
        for (int it = 0; it < 4; it++) {
            int lin = it * 256 + tid;
            int row = lin >> 3, j = lin & 7;
            cp16(&KsB[s * KSTG + row * KSTR + j * 4],
                 Kb + (size_t)(ck * KCH + row) * D3 + j * 8);
        }
        CP_COMMIT();
    };
    auto issueKV = [&](int ck, int s) {
#pragma unroll
        for (int it = 0; it < 4; it++) {
            int lin = it * 256 + tid;
            int row = lin >> 3, j = lin & 7;
            cp16(&KsB[s * KSTG + row * KSTR + j * 4],
                 Kb + (size_t)(ck * KCH + row) * D3 + j * 8);
            cp16(&VsB[s * KSTG + row * KSTR + j * 4],
                 Vb + (size_t)(ck * KCH + row) * D3 + j * 8);
        }
        CP_COMMIT();
    };

    // ---- stage Q (pre-scaled fp16) into K stage 0, extract A fragments
    {
#pragma unroll
        for (int it = 0; it < 4; it++) {
            int lin = it * 256 + tid;
            int row = lin >> 3, j = lin & 7;
            *reinterpret_cast<uint4*>(KsB + row * KSTR + j * 4) =
                *(reinterpret_cast<const uint4*>(Qb + (size_t)(m0 + row) * D3) + j);
        }
    }
    __syncthreads();
    unsigned qf[4][4];
    {
        const int a_row = (ln & 7) + ((ln >> 3) & 1) * 8;
        const int a_k   = (ln >> 4) * 4;
        const int qr = wm + a_row;
#pragma unroll
        for (int kc = 0; kc < 4; kc++)
            ldm_x4(qf[kc][0], qf[kc][1], qf[kc][2], qf[kc][3],
                   ks_base + (uint32_t)((qr * KSTR + kc * 8 + a_k) * 4));
    }
    __syncthreads();

    // ---- pass 1: rowsums of exp2(s)
    issueK(0, 0);
    issueK(1, 1);

    float rsum0 = 0.f, rsum1 = 0.f;
    for (int ck = 0; ck < 16; ck++) {
        CP_WAIT1();
        __syncthreads();
        if (ck + 2 < 16) issueK(ck + 2, (ck + 2) % 3);
        else CP_COMMIT();

        const uint32_t ks = ks_base + (uint32_t)((ck % 3) * KSTG * 4);
#pragma unroll
        for (int np = 0; np < 8; np++) {
            float s0[4] = {0.f, 0.f, 0.f, 0.f};
            float s1[4] = {0.f, 0.f, 0.f, 0.f};
#pragma unroll
            for (int kc = 0; kc < 4; kc++) {
                unsigned b00, b01, b10, b11;
                ldm_x4(b00, b01, b10, b11,
                       ks + (uint32_t)(((np * 16 + b_row) * KSTR + kc * 8 + b_k) * 4));
                mma_f16(s0, qf[kc][0], qf[kc][1], qf[kc][2], qf[kc][3], b00, b01);
                mma_f16(s1, qf[kc][0], qf[kc][1], qf[kc][2], qf[kc][3], b10, b11);
            }
            rsum0 += exp2f(s0[0]) + exp2f(s0[1]) + exp2f(s1[0]) + exp2f(s1[1]);
            rsum1 += exp2f(s0[2]) + exp2f(s0[3]) + exp2f(s1[2]) + exp2f(s1[3]);
        }
    }
    rsum0 += __shfl_xor_sync(0xffffffffu, rsum0, 1);
    rsum0 += __shfl_xor_sync(0xffffffffu, rsum0, 2);
    rsum1 += __shfl_xor_sync(0xffffffffu, rsum1, 1);
    rsum1 += __shfl_xor_sync(0xffffffffu, rsum1, 2);
    const float inv0 = 1.0f / rsum0;
    const float inv1 = 1.0f / rsum1;

    __syncthreads();

    // ---- pass 2
    float oacc[8][4];
#pragma unroll
    for (int dt = 0; dt < 8; dt++)
#pragma unroll
        for (int t = 0; t < 4; t++) oacc[dt][t] = 0.f;

    issueKV(0, 0);
    issueKV(1, 1);

    float* Sr0 = S + (size_t)(m0 + wm + gid) * TT + 2 * tig;
    float* Sr1 = S + (size_t)(m0 + wm + gid + 8) * TT + 2 * tig;

    const int li   = ln >> 3;
    const int lsub = ln & 7;
    const uint32_t ldm_off = (uint32_t)(((li & 1) * 8 + lsub) * (KSTR * 4) + ((li >> 1) * 8) * 2);

    for (int ck = 0; ck < 16; ck++) {
        CP_WAIT1();
        __syncthreads();
        if (ck + 2 < 16) issueKV(ck + 2, (ck + 2) % 3);
        else CP_COMMIT();

        const uint32_t ks = ks_base + (uint32_t)((ck % 3) * KSTG * 4);
        const uint32_t vstage = vs_base + (uint32_t)((ck % 3) * KSTG * 4);

#pragma unroll
        for (int j = 0; j < 8; j++) {      // 16 keys per j
            float s0[4] = {0.f, 0.f, 0.f, 0.f};
            float s1[4] = {0.f, 0.f, 0.f, 0.f};
#pragma unroll
            for (int kc = 0; kc < 4; kc++) {
                unsigned b00, b01, b10, b11;
                ldm_x4(b00, b01, b10, b11,
                       ks + (uint32_t)(((j * 16 + b_row) * KSTR + kc * 8 + b_k) * 4));
                mma_f16(s0, qf[kc][0], qf[kc][1], qf[kc][2], qf[kc][3], b00, b01);
                mma_f16(s1, qf[kc][0], qf[kc][1], qf[kc][2], qf[kc][3], b10, b11);
            }
            float p00 = exp2f(s0[0]) * inv0;
            float p01 = exp2f(s0[1]) * inv0;
            float p02 = exp2f(s0[2]) * inv1;
            float p03 = exp2f(s0[3]) * inv1;
            float p10 = exp2f(s1[0]) * inv0;
            float p11 = exp2f(s1[1]) * inv0;
            float p12 = exp2f(s1[2]) * inv1;
            float p13 = exp2f(s1[3]) * inv1;

            stcs_f2(Sr0 + ck * KCH + (2 * j) * 8,     p00, p01);
            stcs_f2(Sr1 + ck * KCH + (2 * j) * 8,     p02, p03);
            stcs_f2(Sr0 + ck * KCH + (2 * j + 1) * 8, p10, p11);
            stcs_f2(Sr1 + ck * KCH + (2 * j + 1) * 8, p12, p13);

            unsigned a0 = pack_h2(p00, p01);
            unsigned a1 = pack_h2(p02, p03);
            unsigned a2 = pack_h2(p10, p11);
            unsigned a3 = pack_h2(p12, p13);

            const uint32_t kbase = vstage + (uint32_t)(j * 16 * (KSTR * 4)) + ldm_off;
#pragma unroll
            for (int dtp = 0; dtp < 4; dtp++) {
                unsigned r0, r1, r2, r3;
                asm volatile(
                    "ldmatrix.sync.aligned.m8n8.x4.trans.shared.b16 {%0,%1,%2,%3}, [%4];"
                    : "=r"(r0), "=r"(r1), "=r"(r2), "=r"(r3)
                    : "r"(kbase + (uint32_t)(dtp * 32)));
                mma_f16(oacc[2 * dtp],     a0, a1, a2, a3, r0, r1);
                mma_f16(oacc[2 * dtp + 1], a0, a1, a2, a3, r2, r3);
            }
        }
    }

    // ---- epilogue
    __half* Ob = g_valsh + (size_t)b * TT * DD + h * 64;
#pragma unroll
    for (int dt = 0; dt < 8; dt++) {
        *reinterpret_cast<__half2*>(Ob + (size_t)(m0 + wm + gid) * DD + dt * 8 + 2 * tig) =
            __floats2half2_rn(oacc[dt][0], oacc[dt][1]);
        *reinterpret_cast<__half2*>(Ob + (size_t)(m0 + wm + gid + 8) * DD + dt * 8 + 2 * tig) =
            __floats2half2_rn(oacc[dt][2], oacc[dt][3]);
    }
}

// ---------------------------------------------------------------------------
extern "C" void kernel_launch(void* const* d_in, const int* in_sizes, int n_in,
                              void* d_out, int out_size)
{
    const float* x      = (const float*)d_in[0];
    const float* W_qkv  = (const float*)d_in[1];
    const float* b_qkv  = (const float*)d_in[2];
    const float* W_out  = (const float*)d_in[3];
    const float* b_out  = (const float*)d_in[4];

    float* out  = (float*)d_out;
    float* attn = out + (size_t)BB * TT * DD;

    static __half *xh = nullptr, *wqkvh = nullptr, *wouth = nullptr,
                  *qkvh = nullptr, *valsh = nullptr;
    static bool inited = false;
    if (!inited) {
        cudaGetSymbolAddress((void**)&xh, g_xh);
        cudaGetSymbolAddress((void**)&wqkvh, g_wqkvh);
        cudaGetSymbolAddress((void**)&wouth, g_wouth);
        cudaGetSymbolAddress((void**)&qkvh, g_qkvh);
        cudaGetSymbolAddress((void**)&valsh, g_valsh);
        cudaFuncSetAttribute(fused_attn, cudaFuncAttributeMaxDynamicSharedMemorySize, ATTN_SMEM);
        cudaFuncSetAttribute(fused_attn, cudaFuncAttributePreferredSharedMemoryCarveout, 100);
        cudaFuncSetAttribute(gemm_f16<true, true>,   cudaFuncAttributeMaxDynamicSharedMemorySize, GEMM_SMEM);
        cudaFuncSetAttribute(gemm_f16<true, true>,   cudaFuncAttributePreferredSharedMemoryCarveout, 100);
        cudaFuncSetAttribute(gemm_f16<false, false>, cudaFuncAttributeMaxDynamicSharedMemorySize, GEMM_SMEM);
        cudaFuncSetAttribute(gemm_f16<false, false>, cudaFuncAttributePreferredSharedMemoryCarveout, 100);
        inited = true;
    }

    // 0) Prep: x -> fp16; weights -> transposed fp16
    {
        int n4x = (BB * TT * DD) / 4;
        round_f16_kernel<<<(n4x + 255) / 256, 256>>>((const float4*)x, (__half2*)xh, n4x);
        transpose_f16_kernel<<<dim3(D3 / 32, DD / 32), dim3(32, 8)>>>(W_qkv, wqkvh, DD, D3);
        transpose_f16_kernel<<<dim3(DD / 32, DD / 32), dim3(32, 8)>>>(W_out, wouth, DD, DD);
    }

    // 1) QKV projection (fp16 in/out; Q columns pre-scaled by 0.125*log2e)
    gemm_f16<true, true><<<dim3(D3 / 128, (BB * TT) / 128), 256, GEMM_SMEM>>>(
        xh, wqkvh, b_qkv, qkvh, BB * TT, D3, DD);

    // 2) Fused scores + softmax + AV
    fused_attn<<<dim3(TT / 128, BB * HH), 256, ATTN_SMEM>>>(attn);

    // 3) Output projection (fp16 in, fp32 out)
    gemm_f16<false, false><<<dim3(DD / 128, (BB * TT) / 128), 256, GEMM_SMEM>>>(
        valsh, wouth, b_out, out, BB * TT, DD, DD);
}